// round 10
// baseline (speedup 1.0000x reference)
#include <cuda_runtime.h>
#include <cuda_bf16.h>
#include <cstdint>

namespace {
constexpr int Bn = 4, Hn = 16, S = 2048, Dh = 64;
constexpr int BH = Bn * Hn;
constexpr int MQ = 128;
constexpr int NKA = 128;          // pass A keys per tile
constexpr int NTA = S / NKA;      // 16
constexpr int NK = 64;            // pass B keys per tile
constexpr int NT = S / NK;        // 32
constexpr int THREADS = 256;
constexpr int NELEM = BH * S * Dh;
constexpr float LOG2E = 1.4426950408889634f;
constexpr int NUNITS = BH * (S / MQ);   // 1024 units per pass
constexpr int GRID = 296;               // 2 CTAs/SM x 148 SMs (persistent)

constexpr int OFF_K   = 0;              // [2 buf][16KB]
constexpr int OFF_V   = 32768;          // [2 buf][16KB]
constexpr int OFF_MS  = 65536;          // 2048 f32
constexpr unsigned SMEM_BYTES = OFF_MS + S * 4;   // 73,728 B -> 2 CTAs/SM
}

__device__ __nv_bfloat16 g_Qhi[NELEM], g_Qlo[NELEM];
__device__ __nv_bfloat16 g_Khi[NELEM], g_Klo[NELEM];
__device__ __nv_bfloat16 g_VThi[NELEM], g_VTlo[NELEM];   // [bh][d][s]

__device__ unsigned g_ctr;
__device__ unsigned g_flag[NUNITS];
__device__ float    g_linv[NUNITS][MQ];

__device__ __forceinline__ uint32_t s2u(const void* p) {
    uint32_t a;
    asm("{ .reg .u64 t; cvta.to.shared.u64 t, %1; cvt.u32.u64 %0, t; }" : "=r"(a) : "l"(p));
    return a;
}
__device__ __forceinline__ uint32_t swz(uint32_t o) { return o ^ ((o >> 3) & 0x70); }

#define LDSM4(r, a) \
    asm volatile("ldmatrix.sync.aligned.m8n8.x4.shared.b16 {%0,%1,%2,%3},[%4];" \
                 : "=r"((r)[0]), "=r"((r)[1]), "=r"((r)[2]), "=r"((r)[3]) : "r"(a))
#define CP16(dst, src) \
    asm volatile("cp.async.ca.shared.global [%0], [%1], 16;" :: "r"(dst), "l"(src))
#define CP_COMMIT() asm volatile("cp.async.commit_group;" ::: "memory")
#define CP_WAIT0()  asm volatile("cp.async.wait_group 0;" ::: "memory")
#define CP_WAIT1()  asm volatile("cp.async.wait_group 1;" ::: "memory")
// evict-first streaming store of a float2 (keeps K/V resident in L2)
#define STG64_CS(ptr, a, b) \
    asm volatile("st.global.cs.v2.f32 [%0], {%1,%2};" :: "l"(ptr), "f"(a), "f"(b) : "memory")

__device__ __forceinline__ void mma_bf16(float c[4], const uint32_t a[4],
                                         uint32_t b0, uint32_t b1) {
    asm volatile(
        "mma.sync.aligned.m16n8k16.row.col.f32.bf16.bf16.f32 "
        "{%0,%1,%2,%3},{%4,%5,%6,%7},{%8,%9},{%0,%1,%2,%3};"
        : "+f"(c[0]), "+f"(c[1]), "+f"(c[2]), "+f"(c[3])
        : "r"(a[0]), "r"(a[1]), "r"(a[2]), "r"(a[3]), "r"(b0), "r"(b1));
}

__device__ __forceinline__ float ex2f(float x) {
    float r;
    asm("ex2.approx.ftz.f32 %0, %1;" : "=f"(r) : "f"(x));
    return r;
}

// integer-trick bf16 hi/lo split of a pair; hi via round-half-up (residual near-exact)
__device__ __forceinline__ void pack2(float x, float y, uint32_t& hi, uint32_t& lo) {
    uint32_t rx = __float_as_uint(x) + 0x8000u;
    uint32_t ry = __float_as_uint(y) + 0x8000u;
    hi = __byte_perm(rx, ry, 0x7632);
    float hx = __uint_as_float(rx & 0xFFFF0000u);
    float hy = __uint_as_float(ry & 0xFFFF0000u);
    asm("cvt.rn.bf16x2.f32 %0, %1, %2;" : "=r"(lo) : "f"(y - hy), "f"(x - hx));
}

__device__ __forceinline__ void fsplit(float x, __nv_bfloat16& h, __nv_bfloat16& l) {
    h = __float2bfloat16_rn(x);
    l = __float2bfloat16_rn(x - __bfloat162float(h));
}
__device__ __forceinline__ uint32_t pack_hi(float x, float y) {
    __nv_bfloat162 t;
    t.x = __float2bfloat16_rn(x);
    t.y = __float2bfloat16_rn(y);
    return *reinterpret_cast<uint32_t*>(&t);
}
__device__ __forceinline__ uint32_t pack_lo(float x, float y) {
    __nv_bfloat162 t;
    t.x = __float2bfloat16_rn(x - __bfloat162float(__float2bfloat16_rn(x)));
    t.y = __float2bfloat16_rn(y - __bfloat162float(__float2bfloat16_rn(y)));
    return *reinterpret_cast<uint32_t*>(&t);
}

// ---------------- pre-kernels ----------------
__global__ void conv_qk(const float* __restrict__ q, const float* __restrict__ k) {
    // per-launch reset of the persistent-queue state (runs before attn_persist)
    if (blockIdx.x == 0) {
        if (threadIdx.x == 0) g_ctr = 0u;
        for (int i = threadIdx.x; i < NUNITS; i += blockDim.x) g_flag[i] = 0u;
    }
    size_t i4 = (size_t)blockIdx.x * blockDim.x + threadIdx.x;
    size_t e = i4 * 4;
    float4 qv = *reinterpret_cast<const float4*>(q + e);
    float4 kv = *reinterpret_cast<const float4*>(k + e);
    qv.x *= 0.125f; qv.y *= 0.125f; qv.z *= 0.125f; qv.w *= 0.125f;
    uint2 w;
    w.x = pack_hi(qv.x, qv.y); w.y = pack_hi(qv.z, qv.w);
    *reinterpret_cast<uint2*>(g_Qhi + e) = w;
    w.x = pack_lo(qv.x, qv.y); w.y = pack_lo(qv.z, qv.w);
    *reinterpret_cast<uint2*>(g_Qlo + e) = w;
    w.x = pack_hi(kv.x, kv.y); w.y = pack_hi(kv.z, kv.w);
    *reinterpret_cast<uint2*>(g_Khi + e) = w;
    w.x = pack_lo(kv.x, kv.y); w.y = pack_lo(kv.z, kv.w);
    *reinterpret_cast<uint2*>(g_Klo + e) = w;
}

__global__ void conv_vt(const float* __restrict__ v) {
    __shared__ float t[32][33];
    const int bh = blockIdx.z, s0 = blockIdx.x * 32, d0 = blockIdx.y * 32;
    const int tx = threadIdx.x, ty = threadIdx.y;   // (32, 8)
    #pragma unroll
    for (int j = 0; j < 4; ++j)
        t[ty + 8 * j][tx] = v[((size_t)bh * S + s0 + ty + 8 * j) * Dh + d0 + tx];
    __syncthreads();
    #pragma unroll
    for (int j = 0; j < 4; ++j) {
        float x = t[tx][ty + 8 * j];
        __nv_bfloat16 h, l;
        fsplit(x, h, l);
        size_t o = ((size_t)bh * Dh + d0 + ty + 8 * j) * S + s0 + tx;
        g_VThi[o] = h; g_VTlo[o] = l;
    }
}

// ---------------- persistent main kernel ----------------
__global__ __launch_bounds__(THREADS, 2)
void attn_persist(const int* __restrict__ mask, float* __restrict__ out,
                  float* __restrict__ p_attn)
{
    extern __shared__ char sm[];
    __shared__ unsigned s_uid;
    const uint32_t sb = s2u(sm);
    const int tid = threadIdx.x;
    const int w = tid >> 5, lane = tid & 31;
    const int rev = (w >> 2) & 1;   // warps 4-7 walk chunks in reverse (SMSP partner skew)
    float* msf = reinterpret_cast<float*>(sm + OFF_MS);

    for (;;) {
        __syncthreads();   // previous unit fully done with smem + s_uid
        if (tid == 0) s_uid = atomicAdd(&g_ctr, 1u);
        __syncthreads();
        const unsigned uid = s_uid;
        if (uid >= 2u * NUNITS) break;
        const bool isA = uid < (unsigned)NUNITS;
        const int u  = isA ? (int)uid : (int)(uid - NUNITS);
        const int qt = u & 15, bh = u >> 4;
        const int b  = bh >> 4;
        const int q0 = qt * MQ;

        // mask row for this batch
        for (int i = tid; i < S; i += THREADS)
            msf[i] = (mask[b * S + i] != 0) ? 1.0f : 0.0f;

        if (isA) {
            // ======== PASS A UNIT: rowsums (1-term, K-hi only) ========
            #pragma unroll
            for (int i = 0; i < 4; ++i) {   // stage Q-hi
                int fi = tid + i * THREADS;
                int row = fi >> 3, c8 = fi & 7;
                CP16(sb + OFF_K + swz((uint32_t)(row * 128 + c8 * 16)),
                     g_Qhi + ((size_t)bh * S + q0 + row) * Dh + c8 * 8);
            }
            CP_COMMIT(); CP_WAIT0(); __syncthreads();
            uint32_t qa0[4][4];
            #pragma unroll
            for (int ks = 0; ks < 4; ++ks) {
                uint32_t a = sb + OFF_K +
                    swz((uint32_t)((w * 16 + (lane & 15)) * 128 + ks * 32 +
                                   ((lane >> 4) & 1) * 16));
                LDSM4(qa0[ks], a);
            }
            __syncthreads();

            float rs0 = 0.f, rs1 = 0.f;
            #pragma unroll
            for (int i = 0; i < 4; ++i) {   // preload tile 0
                int fi = tid + i * THREADS;
                int row = fi >> 3, c8 = fi & 7;
                CP16(sb + OFF_K + swz((uint32_t)(row * 128 + c8 * 16)),
                     g_Khi + ((size_t)bh * S + row) * Dh + c8 * 8);
            }
            CP_COMMIT();
            for (int t = 0; t < NTA; ++t) {
                const int t0 = t * NKA;
                if (t + 1 < NTA) {
                    const uint32_t dstb = sb + OFF_K + ((t + 1) & 1) * 16384;
                    #pragma unroll
                    for (int i = 0; i < 4; ++i) {
                        int fi = tid + i * THREADS;
                        int row = fi >> 3, c8 = fi & 7;
                        CP16(dstb + swz((uint32_t)(row * 128 + c8 * 16)),
                             g_Khi + ((size_t)bh * S + t0 + NKA + row) * Dh + c8 * 8);
                    }
                    CP_COMMIT(); CP_WAIT1();
                } else {
                    CP_WAIT0();
                }
                __syncthreads();
                const uint32_t kbase = sb + OFF_K + (t & 1) * 16384;
                #pragma unroll
                for (int g = 0; g < 8; ++g) {
                    const int gg = rev ? 7 - g : g;
                    float c0[4] = {0.f, 0.f, 0.f, 0.f};
                    float c1[4] = {0.f, 0.f, 0.f, 0.f};
                    uint32_t rowb = gg * 16 + (lane & 15);
                    #pragma unroll
                    for (int ks = 0; ks < 4; ++ks) {
                        uint32_t kh[4];
                        LDSM4(kh, kbase + swz(rowb * 128 + ks * 32 + ((lane >> 4) & 1) * 16));
                        mma_bf16(c0, qa0[ks], kh[0], kh[2]);
                        mma_bf16(c1, qa0[ks], kh[1], kh[3]);
                    }
                    int colA = t0 + gg * 16 + 2 * (lane & 3);
                    float2 mA = *reinterpret_cast<const float2*>(msf + colA);
                    float2 mB = *reinterpret_cast<const float2*>(msf + colA + 8);
                    rs0 += mA.x * ex2f(c0[0] * LOG2E) + mA.y * ex2f(c0[1] * LOG2E);
                    rs1 += mA.x * ex2f(c0[2] * LOG2E) + mA.y * ex2f(c0[3] * LOG2E);
                    rs0 += mB.x * ex2f(c1[0] * LOG2E) + mB.y * ex2f(c1[1] * LOG2E);
                    rs1 += mB.x * ex2f(c1[2] * LOG2E) + mB.y * ex2f(c1[3] * LOG2E);
                }
                __syncthreads();
            }
            rs0 += __shfl_xor_sync(0xffffffffu, rs0, 1);
            rs0 += __shfl_xor_sync(0xffffffffu, rs0, 2);
            rs1 += __shfl_xor_sync(0xffffffffu, rs1, 1);
            rs1 += __shfl_xor_sync(0xffffffffu, rs1, 2);
            if ((lane & 3) == 0) {
                g_linv[u][w * 16 + (lane >> 2)]     = -__log2f(rs0);
                g_linv[u][w * 16 + 8 + (lane >> 2)] = -__log2f(rs1);
            }
            __syncthreads();
            __threadfence();                       // release: linv visible before flag
            if (tid == 0) atomicExch(&g_flag[u], 1u);
        } else {
            // ======== PASS B UNIT: p_attn + out (3-term QK, fused PV) ========
            #pragma unroll
            for (int buf = 0; buf < 2; ++buf) {    // stage Q hi/lo
                const __nv_bfloat16* src = buf ? g_Qlo : g_Qhi;
                #pragma unroll
                for (int i = 0; i < 4; ++i) {
                    int fi = tid + i * THREADS;
                    int row = fi >> 3, c8 = fi & 7;
                    CP16(sb + OFF_K + buf * 16384 + swz((uint32_t)(row * 128 + c8 * 16)),
                         src + ((size_t)bh * S + q0 + row) * Dh + c8 * 8);
                }
            }
            CP_COMMIT(); CP_WAIT0(); __syncthreads();
            uint32_t qa[2][4][4];
            #pragma unroll
            for (int buf = 0; buf < 2; ++buf)
                #pragma unroll
                for (int ks = 0; ks < 4; ++ks) {
                    uint32_t a = sb + OFF_K + buf * 16384 +
                        swz((uint32_t)((w * 16 + (lane & 15)) * 128 + ks * 32 +
                                       ((lane >> 4) & 1) * 16));
                    LDSM4(qa[buf][ks], a);
                }
            // acquire rowsums from the matching A unit
            if (tid == 0) {
                while (atomicAdd(&g_flag[u], 0u) == 0u) __nanosleep(200);
                __threadfence();
            }
            __syncthreads();
            const float linv0 = __ldcg(&g_linv[u][w * 16 + (lane >> 2)]);
            const float linv1 = __ldcg(&g_linv[u][w * 16 + 8 + (lane >> 2)]);

            float oacc[8][4];
            #pragma unroll
            for (int d = 0; d < 8; ++d)
                #pragma unroll
                for (int e = 0; e < 4; ++e) oacc[d][e] = 0.f;

            const int r0g = q0 + w * 16 + (lane >> 2);
            float* pa_row0 = p_attn + ((size_t)bh * S + r0g) * S;
            float* pa_row1 = p_attn + ((size_t)bh * S + r0g + 8) * S;

            auto loadB = [&](int t, int buf) {
                const int t0 = t * NK;
                const uint32_t kbuf = sb + OFF_K + buf * 16384;
                const uint32_t vbuf = sb + OFF_V + buf * 16384;
                #pragma unroll
                for (int hilo = 0; hilo < 2; ++hilo) {
                    const __nv_bfloat16* ksrc = hilo ? g_Klo : g_Khi;
                    const __nv_bfloat16* vsrc = hilo ? g_VTlo : g_VThi;
                    #pragma unroll
                    for (int i = 0; i < 2; ++i) {
                        int fi = tid + i * THREADS;
                        int row = fi >> 3, c8 = fi & 7;
                        uint32_t soff = swz((uint32_t)(row * 128 + c8 * 16));
                        CP16(kbuf + hilo * 8192 + soff,
                             ksrc + ((size_t)bh * S + t0 + row) * Dh + c8 * 8);
                        CP16(vbuf + hilo * 8192 + soff,
                             vsrc + ((size_t)bh * Dh + row) * S + t0 + c8 * 8);
                    }
                }
            };

            __syncthreads();   // Q staging reads done before K tiles overwrite
            loadB(0, 0); CP_COMMIT();
            for (int t = 0; t < NT; ++t) {
                const int t0 = t * NK;
                if (t + 1 < NT) { loadB(t + 1, (t + 1) & 1); CP_COMMIT(); CP_WAIT1(); }
                else            { CP_WAIT0(); }
                __syncthreads();
                const uint32_t kb = sb + OFF_K + (t & 1) * 16384;
                const uint32_t vb = sb + OFF_V + (t & 1) * 16384;

                #pragma unroll
                for (int g = 0; g < 4; ++g) {
                    const int gg = rev ? 3 - g : g;
                    float c0[4] = {0.f, 0.f, 0.f, 0.f};
                    float c1[4] = {0.f, 0.f, 0.f, 0.f};
                    uint32_t rowb = gg * 16 + (lane & 15);
                    #pragma unroll
                    for (int ks = 0; ks < 4; ++ks) {
                        uint32_t ah2 = kb + swz(rowb * 128 + ks * 32 + ((lane >> 4) & 1) * 16);
                        uint32_t kh[4], kl[4];
                        LDSM4(kh, ah2);
                        LDSM4(kl, ah2 + 8192);
                        mma_bf16(c0, qa[0][ks], kh[0], kh[2]);
                        mma_bf16(c0, qa[0][ks], kl[0], kl[2]);
                        mma_bf16(c0, qa[1][ks], kh[0], kh[2]);
                        mma_bf16(c1, qa[0][ks], kh[1], kh[3]);
                        mma_bf16(c1, qa[0][ks], kl[1], kl[3]);
                        mma_bf16(c1, qa[1][ks], kh[1], kh[3]);
                    }
                    int colA = t0 + gg * 16 + 2 * (lane & 3);
                    float2 mA = *reinterpret_cast<const float2*>(msf + colA);
                    float2 mB = *reinterpret_cast<const float2*>(msf + colA + 8);
                    float p00 = mA.x * ex2f(fmaf(c0[0], LOG2E, linv0));
                    float p01 = mA.y * ex2f(fmaf(c0[1], LOG2E, linv0));
                    float p10 = mA.x * ex2f(fmaf(c0[2], LOG2E, linv1));
                    float p11 = mA.y * ex2f(fmaf(c0[3], LOG2E, linv1));
                    float q00 = mB.x * ex2f(fmaf(c1[0], LOG2E, linv0));
                    float q01 = mB.y * ex2f(fmaf(c1[1], LOG2E, linv0));
                    float q10 = mB.x * ex2f(fmaf(c1[2], LOG2E, linv1));
                    float q11 = mB.y * ex2f(fmaf(c1[3], LOG2E, linv1));
                    STG64_CS(pa_row0 + colA,     p00, p01);
                    STG64_CS(pa_row0 + colA + 8, q00, q01);
                    STG64_CS(pa_row1 + colA,     p10, p11);
                    STG64_CS(pa_row1 + colA + 8, q10, q11);
                    uint32_t ah[4], al[4];
                    pack2(p00, p01, ah[0], al[0]);
                    pack2(p10, p11, ah[1], al[1]);
                    pack2(q00, q01, ah[2], al[2]);
                    pack2(q10, q11, ah[3], al[3]);
                    uint32_t kcb = gg * 32 + ((lane >> 4) & 1) * 16;
                    #pragma unroll
                    for (int db2 = 0; db2 < 4; ++db2) {
                        uint32_t vaddr = vb + swz((uint32_t)((db2 * 16 + (lane & 15)) * 128) + kcb);
                        uint32_t vh[4], vl[4];
                        LDSM4(vh, vaddr);
                        LDSM4(vl, vaddr + 8192);
                        mma_bf16(oacc[db2 * 2],     ah, vh[0], vh[2]);
                        mma_bf16(oacc[db2 * 2],     ah, vl[0], vl[2]);
                        mma_bf16(oacc[db2 * 2],     al, vh[0], vh[2]);
                        mma_bf16(oacc[db2 * 2 + 1], ah, vh[1], vh[3]);
                        mma_bf16(oacc[db2 * 2 + 1], ah, vl[1], vl[3]);
                        mma_bf16(oacc[db2 * 2 + 1], al, vh[1], vh[3]);
                    }
                }
                __syncthreads();
            }
            #pragma unroll
            for (int db = 0; db < 8; ++db) {
                int col = db * 8 + 2 * (lane & 3);
                STG64_CS(out + ((size_t)bh * S + r0g) * Dh + col,
                         oacc[db][0], oacc[db][1]);
                STG64_CS(out + ((size_t)bh * S + r0g + 8) * Dh + col,
                         oacc[db][2], oacc[db][3]);
            }
        }
    }
}

extern "C" void kernel_launch(void* const* d_in, const int* in_sizes, int n_in,
                              void* d_out, int out_size) {
    const float* q = (const float*)d_in[0];
    const float* k = (const float*)d_in[1];
    const float* v = (const float*)d_in[2];
    const int* mask = (const int*)d_in[3];

    float* out = (float*)d_out;
    float* p_attn = out + (size_t)Bn * Hn * S * Dh;

    conv_qk<<<NELEM / 4 / THREADS, THREADS>>>(q, k);
    conv_vt<<<dim3(S / 32, Dh / 32, BH), dim3(32, 8)>>>(v);

    cudaFuncSetAttribute(attn_persist, cudaFuncAttributeMaxDynamicSharedMemorySize, SMEM_BYTES);
    attn_persist<<<GRID, THREADS, SMEM_BYTES>>>(mask, out, p_attn);
}

// round 11
// speedup vs baseline: 1.1219x; 1.1219x over previous
#include <cuda_runtime.h>
#include <cuda_bf16.h>
#include <cuda_fp16.h>
#include <cstdint>

namespace {
constexpr int Bn = 4, Hn = 16, S = 2048, Dh = 64;
constexpr int BH = Bn * Hn;
constexpr int MQ = 128;
constexpr int NKA = 128;          // pass A keys per tile
constexpr int NTA = S / NKA;      // 16
constexpr int NK = 64;            // pass B keys per tile
constexpr int NT = S / NK;        // 32
constexpr int THREADS = 256;
constexpr int NELEM = BH * S * Dh;
constexpr float LOG2E = 1.4426950408889634f;
constexpr int NUNITS = BH * (S / MQ);   // 1024 units per pass
constexpr int GRID = 296;               // 2 CTAs/SM x 148 SMs (persistent)

constexpr int OFF_K   = 0;              // [2 buf][16KB]
constexpr int OFF_V   = 32768;          // [2 buf][16KB]
constexpr int OFF_MS  = 65536;          // 2048 f32
constexpr unsigned SMEM_BYTES = OFF_MS + S * 4;   // 73,728 B -> 2 CTAs/SM
}

__device__ __nv_bfloat16 g_Qhi[NELEM], g_Qlo[NELEM];
__device__ __nv_bfloat16 g_Khi[NELEM], g_Klo[NELEM];
__device__ __half        g_VThi[NELEM], g_VTlo[NELEM];   // [bh][d][s], fp16 2-term

__device__ unsigned g_ctr;
__device__ unsigned g_flag[NUNITS];
__device__ float    g_linv[NUNITS][MQ];

__device__ __forceinline__ uint32_t s2u(const void* p) {
    uint32_t a;
    asm("{ .reg .u64 t; cvta.to.shared.u64 t, %1; cvt.u32.u64 %0, t; }" : "=r"(a) : "l"(p));
    return a;
}
__device__ __forceinline__ uint32_t swz(uint32_t o) { return o ^ ((o >> 3) & 0x70); }

#define LDSM4(r, a) \
    asm volatile("ldmatrix.sync.aligned.m8n8.x4.shared.b16 {%0,%1,%2,%3},[%4];" \
                 : "=r"((r)[0]), "=r"((r)[1]), "=r"((r)[2]), "=r"((r)[3]) : "r"(a))
#define CP16(dst, src) \
    asm volatile("cp.async.ca.shared.global [%0], [%1], 16;" :: "r"(dst), "l"(src))
#define CP_COMMIT() asm volatile("cp.async.commit_group;" ::: "memory")
#define CP_WAIT0()  asm volatile("cp.async.wait_group 0;" ::: "memory")
#define CP_WAIT1()  asm volatile("cp.async.wait_group 1;" ::: "memory")

__device__ __forceinline__ void mma_bf16(float c[4], const uint32_t a[4],
                                         uint32_t b0, uint32_t b1) {
    asm volatile(
        "mma.sync.aligned.m16n8k16.row.col.f32.bf16.bf16.f32 "
        "{%0,%1,%2,%3},{%4,%5,%6,%7},{%8,%9},{%0,%1,%2,%3};"
        : "+f"(c[0]), "+f"(c[1]), "+f"(c[2]), "+f"(c[3])
        : "r"(a[0]), "r"(a[1]), "r"(a[2]), "r"(a[3]), "r"(b0), "r"(b1));
}
__device__ __forceinline__ void mma_f16(float c[4], const uint32_t a[4],
                                        uint32_t b0, uint32_t b1) {
    asm volatile(
        "mma.sync.aligned.m16n8k16.row.col.f32.f16.f16.f32 "
        "{%0,%1,%2,%3},{%4,%5,%6,%7},{%8,%9},{%0,%1,%2,%3};"
        : "+f"(c[0]), "+f"(c[1]), "+f"(c[2]), "+f"(c[3])
        : "r"(a[0]), "r"(a[1]), "r"(a[2]), "r"(a[3]), "r"(b0), "r"(b1));
}

__device__ __forceinline__ float ex2f(float x) {
    float r;
    asm("ex2.approx.ftz.f32 %0, %1;" : "=f"(r) : "f"(x));
    return r;
}
// pack two f32 into f16x2: lo = x, hi = y
__device__ __forceinline__ uint32_t packh2(float x, float y) {
    uint32_t r;
    asm("cvt.rn.f16x2.f32 %0, %1, %2;" : "=r"(r) : "f"(y), "f"(x));
    return r;
}

__device__ __forceinline__ void fsplit(float x, __nv_bfloat16& h, __nv_bfloat16& l) {
    h = __float2bfloat16_rn(x);
    l = __float2bfloat16_rn(x - __bfloat162float(h));
}
__device__ __forceinline__ uint32_t pack_hi(float x, float y) {
    __nv_bfloat162 t;
    t.x = __float2bfloat16_rn(x);
    t.y = __float2bfloat16_rn(y);
    return *reinterpret_cast<uint32_t*>(&t);
}
__device__ __forceinline__ uint32_t pack_lo(float x, float y) {
    __nv_bfloat162 t;
    t.x = __float2bfloat16_rn(x - __bfloat162float(__float2bfloat16_rn(x)));
    t.y = __float2bfloat16_rn(y - __bfloat162float(__float2bfloat16_rn(y)));
    return *reinterpret_cast<uint32_t*>(&t);
}

// ---------------- pre-kernels ----------------
__global__ void conv_qk(const float* __restrict__ q, const float* __restrict__ k) {
    // per-launch reset of the persistent-queue state (runs before attn_persist)
    if (blockIdx.x == 0) {
        if (threadIdx.x == 0) g_ctr = 0u;
        for (int i = threadIdx.x; i < NUNITS; i += blockDim.x) g_flag[i] = 0u;
    }
    size_t i4 = (size_t)blockIdx.x * blockDim.x + threadIdx.x;
    size_t e = i4 * 4;
    float4 qv = *reinterpret_cast<const float4*>(q + e);
    float4 kv = *reinterpret_cast<const float4*>(k + e);
    qv.x *= 0.125f; qv.y *= 0.125f; qv.z *= 0.125f; qv.w *= 0.125f;
    uint2 w;
    w.x = pack_hi(qv.x, qv.y); w.y = pack_hi(qv.z, qv.w);
    *reinterpret_cast<uint2*>(g_Qhi + e) = w;
    w.x = pack_lo(qv.x, qv.y); w.y = pack_lo(qv.z, qv.w);
    *reinterpret_cast<uint2*>(g_Qlo + e) = w;
    w.x = pack_hi(kv.x, kv.y); w.y = pack_hi(kv.z, kv.w);
    *reinterpret_cast<uint2*>(g_Khi + e) = w;
    w.x = pack_lo(kv.x, kv.y); w.y = pack_lo(kv.z, kv.w);
    *reinterpret_cast<uint2*>(g_Klo + e) = w;
}

__global__ void conv_vt(const float* __restrict__ v) {
    __shared__ float t[32][33];
    const int bh = blockIdx.z, s0 = blockIdx.x * 32, d0 = blockIdx.y * 32;
    const int tx = threadIdx.x, ty = threadIdx.y;   // (32, 8)
    #pragma unroll
    for (int j = 0; j < 4; ++j)
        t[ty + 8 * j][tx] = v[((size_t)bh * S + s0 + ty + 8 * j) * Dh + d0 + tx];
    __syncthreads();
    #pragma unroll
    for (int j = 0; j < 4; ++j) {
        float x = t[tx][ty + 8 * j];
        __half h = __float2half_rn(x);
        __half l = __float2half_rn(x - __half2float(h));
        size_t o = ((size_t)bh * Dh + d0 + ty + 8 * j) * S + s0 + tx;
        g_VThi[o] = h; g_VTlo[o] = l;
    }
}

// ---------------- persistent main kernel ----------------
__global__ __launch_bounds__(THREADS, 2)
void attn_persist(const int* __restrict__ mask, float* __restrict__ out,
                  float* __restrict__ p_attn)
{
    extern __shared__ char sm[];
    __shared__ unsigned s_uid;
    const uint32_t sb = s2u(sm);
    const int tid = threadIdx.x;
    const int w = tid >> 5, lane = tid & 31;
    float* msf = reinterpret_cast<float*>(sm + OFF_MS);

    for (;;) {
        __syncthreads();   // previous unit fully done with smem + s_uid
        if (tid == 0) s_uid = atomicAdd(&g_ctr, 1u);
        __syncthreads();
        const unsigned uid = s_uid;
        if (uid >= 2u * NUNITS) break;
        const bool isA = uid < (unsigned)NUNITS;
        const int u  = isA ? (int)uid : (int)(uid - NUNITS);
        const int qt = u & 15, bh = u >> 4;
        const int b  = bh >> 4;
        const int q0 = qt * MQ;

        // mask row for this batch
        for (int i = tid; i < S; i += THREADS)
            msf[i] = (mask[b * S + i] != 0) ? 1.0f : 0.0f;

        if (isA) {
            // ======== PASS A UNIT: rowsums (1-term, K-hi only) ========
            #pragma unroll
            for (int i = 0; i < 4; ++i) {   // stage Q-hi
                int fi = tid + i * THREADS;
                int row = fi >> 3, c8 = fi & 7;
                CP16(sb + OFF_K + swz((uint32_t)(row * 128 + c8 * 16)),
                     g_Qhi + ((size_t)bh * S + q0 + row) * Dh + c8 * 8);
            }
            CP_COMMIT(); CP_WAIT0(); __syncthreads();
            uint32_t qa0[4][4];
            #pragma unroll
            for (int ks = 0; ks < 4; ++ks) {
                uint32_t a = sb + OFF_K +
                    swz((uint32_t)((w * 16 + (lane & 15)) * 128 + ks * 32 +
                                   ((lane >> 4) & 1) * 16));
                LDSM4(qa0[ks], a);
            }
            __syncthreads();

            float rs0 = 0.f, rs1 = 0.f;
            #pragma unroll
            for (int i = 0; i < 4; ++i) {   // preload tile 0
                int fi = tid + i * THREADS;
                int row = fi >> 3, c8 = fi & 7;
                CP16(sb + OFF_K + swz((uint32_t)(row * 128 + c8 * 16)),
                     g_Khi + ((size_t)bh * S + row) * Dh + c8 * 8);
            }
            CP_COMMIT();
            for (int t = 0; t < NTA; ++t) {
                const int t0 = t * NKA;
                if (t + 1 < NTA) {
                    const uint32_t dstb = sb + OFF_K + ((t + 1) & 1) * 16384;
                    #pragma unroll
                    for (int i = 0; i < 4; ++i) {
                        int fi = tid + i * THREADS;
                        int row = fi >> 3, c8 = fi & 7;
                        CP16(dstb + swz((uint32_t)(row * 128 + c8 * 16)),
                             g_Khi + ((size_t)bh * S + t0 + NKA + row) * Dh + c8 * 8);
                    }
                    CP_COMMIT(); CP_WAIT1();
                } else {
                    CP_WAIT0();
                }
                __syncthreads();
                const uint32_t kbase = sb + OFF_K + (t & 1) * 16384;
                #pragma unroll
                for (int g = 0; g < 8; ++g) {
                    float c0[4] = {0.f, 0.f, 0.f, 0.f};
                    float c1[4] = {0.f, 0.f, 0.f, 0.f};
                    uint32_t rowb = g * 16 + (lane & 15);
                    #pragma unroll
                    for (int ks = 0; ks < 4; ++ks) {
                        uint32_t kh[4];
                        LDSM4(kh, kbase + swz(rowb * 128 + ks * 32 + ((lane >> 4) & 1) * 16));
                        mma_bf16(c0, qa0[ks], kh[0], kh[2]);
                        mma_bf16(c1, qa0[ks], kh[1], kh[3]);
                    }
                    int colA = t0 + g * 16 + 2 * (lane & 3);
                    float2 mA = *reinterpret_cast<const float2*>(msf + colA);
                    float2 mB = *reinterpret_cast<const float2*>(msf + colA + 8);
                    rs0 += mA.x * ex2f(c0[0] * LOG2E) + mA.y * ex2f(c0[1] * LOG2E);
                    rs1 += mA.x * ex2f(c0[2] * LOG2E) + mA.y * ex2f(c0[3] * LOG2E);
                    rs0 += mB.x * ex2f(c1[0] * LOG2E) + mB.y * ex2f(c1[1] * LOG2E);
                    rs1 += mB.x * ex2f(c1[2] * LOG2E) + mB.y * ex2f(c1[3] * LOG2E);
                }
                __syncthreads();
            }
            rs0 += __shfl_xor_sync(0xffffffffu, rs0, 1);
            rs0 += __shfl_xor_sync(0xffffffffu, rs0, 2);
            rs1 += __shfl_xor_sync(0xffffffffu, rs1, 1);
            rs1 += __shfl_xor_sync(0xffffffffu, rs1, 2);
            if ((lane & 3) == 0) {
                g_linv[u][w * 16 + (lane >> 2)]     = -__log2f(rs0);
                g_linv[u][w * 16 + 8 + (lane >> 2)] = -__log2f(rs1);
            }
            __syncthreads();
            __threadfence();                       // release: linv visible before flag
            if (tid == 0) atomicExch(&g_flag[u], 1u);
        } else {
            // ======== PASS B UNIT: p_attn + out (3-term QK, fp16 2-MMA PV) ========
            #pragma unroll
            for (int buf = 0; buf < 2; ++buf) {    // stage Q hi/lo
                const __nv_bfloat16* src = buf ? g_Qlo : g_Qhi;
                #pragma unroll
                for (int i = 0; i < 4; ++i) {
                    int fi = tid + i * THREADS;
                    int row = fi >> 3, c8 = fi & 7;
                    CP16(sb + OFF_K + buf * 16384 + swz((uint32_t)(row * 128 + c8 * 16)),
                         src + ((size_t)bh * S + q0 + row) * Dh + c8 * 8);
                }
            }
            CP_COMMIT(); CP_WAIT0(); __syncthreads();
            uint32_t qa[2][4][4];
            #pragma unroll
            for (int buf = 0; buf < 2; ++buf)
                #pragma unroll
                for (int ks = 0; ks < 4; ++ks) {
                    uint32_t a = sb + OFF_K + buf * 16384 +
                        swz((uint32_t)((w * 16 + (lane & 15)) * 128 + ks * 32 +
                                       ((lane >> 4) & 1) * 16));
                    LDSM4(qa[buf][ks], a);
                }
            // acquire rowsums from the matching A unit
            if (tid == 0) {
                while (atomicAdd(&g_flag[u], 0u) == 0u) __nanosleep(200);
                __threadfence();
            }
            __syncthreads();
            const float linv0 = __ldcg(&g_linv[u][w * 16 + (lane >> 2)]);
            const float linv1 = __ldcg(&g_linv[u][w * 16 + 8 + (lane >> 2)]);

            float oacc[8][4];
            #pragma unroll
            for (int d = 0; d < 8; ++d)
                #pragma unroll
                for (int e = 0; e < 4; ++e) oacc[d][e] = 0.f;

            const int r0g = q0 + w * 16 + (lane >> 2);
            float* pa_row0 = p_attn + ((size_t)bh * S + r0g) * S;
            float* pa_row1 = p_attn + ((size_t)bh * S + r0g + 8) * S;

            auto loadB = [&](int t, int buf) {
                const int t0 = t * NK;
                const uint32_t kbuf = sb + OFF_K + buf * 16384;
                const uint32_t vbuf = sb + OFF_V + buf * 16384;
                #pragma unroll
                for (int hilo = 0; hilo < 2; ++hilo) {
                    const __nv_bfloat16* ksrc = hilo ? g_Klo : g_Khi;
                    const __half*        vsrc = hilo ? g_VTlo : g_VThi;
                    #pragma unroll
                    for (int i = 0; i < 2; ++i) {
                        int fi = tid + i * THREADS;
                        int row = fi >> 3, c8 = fi & 7;
                        uint32_t soff = swz((uint32_t)(row * 128 + c8 * 16));
                        CP16(kbuf + hilo * 8192 + soff,
                             ksrc + ((size_t)bh * S + t0 + row) * Dh + c8 * 8);
                        CP16(vbuf + hilo * 8192 + soff,
                             vsrc + ((size_t)bh * Dh + row) * S + t0 + c8 * 8);
                    }
                }
            };

            __syncthreads();   // Q staging reads done before K tiles overwrite
            loadB(0, 0); CP_COMMIT();
            for (int t = 0; t < NT; ++t) {
                const int t0 = t * NK;
                if (t + 1 < NT) { loadB(t + 1, (t + 1) & 1); CP_COMMIT(); CP_WAIT1(); }
                else            { CP_WAIT0(); }
                __syncthreads();
                const uint32_t kb = sb + OFF_K + (t & 1) * 16384;
                const uint32_t vb = sb + OFF_V + (t & 1) * 16384;

                #pragma unroll
                for (int g = 0; g < 4; ++g) {
                    float c0[4] = {0.f, 0.f, 0.f, 0.f};
                    float c1[4] = {0.f, 0.f, 0.f, 0.f};
                    uint32_t rowb = g * 16 + (lane & 15);
                    #pragma unroll
                    for (int ks = 0; ks < 4; ++ks) {
                        uint32_t ah2 = kb + swz(rowb * 128 + ks * 32 + ((lane >> 4) & 1) * 16);
                        uint32_t kh[4], kl[4];
                        LDSM4(kh, ah2);
                        LDSM4(kl, ah2 + 8192);
                        mma_bf16(c0, qa[0][ks], kh[0], kh[2]);
                        mma_bf16(c0, qa[0][ks], kl[0], kl[2]);
                        mma_bf16(c0, qa[1][ks], kh[0], kh[2]);
                        mma_bf16(c1, qa[0][ks], kh[1], kh[3]);
                        mma_bf16(c1, qa[0][ks], kl[1], kl[3]);
                        mma_bf16(c1, qa[1][ks], kh[1], kh[3]);
                    }
                    int colA = t0 + g * 16 + 2 * (lane & 3);
                    float2 mA = *reinterpret_cast<const float2*>(msf + colA);
                    float2 mB = *reinterpret_cast<const float2*>(msf + colA + 8);
                    float p00 = mA.x * ex2f(fmaf(c0[0], LOG2E, linv0));
                    float p01 = mA.y * ex2f(fmaf(c0[1], LOG2E, linv0));
                    float p10 = mA.x * ex2f(fmaf(c0[2], LOG2E, linv1));
                    float p11 = mA.y * ex2f(fmaf(c0[3], LOG2E, linv1));
                    float q00 = mB.x * ex2f(fmaf(c1[0], LOG2E, linv0));
                    float q01 = mB.y * ex2f(fmaf(c1[1], LOG2E, linv0));
                    float q10 = mB.x * ex2f(fmaf(c1[2], LOG2E, linv1));
                    float q11 = mB.y * ex2f(fmaf(c1[3], LOG2E, linv1));
                    *reinterpret_cast<float2*>(pa_row0 + colA)     = make_float2(p00, p01);
                    *reinterpret_cast<float2*>(pa_row0 + colA + 8) = make_float2(q00, q01);
                    *reinterpret_cast<float2*>(pa_row1 + colA)     = make_float2(p10, p11);
                    *reinterpret_cast<float2*>(pa_row1 + colA + 8) = make_float2(q10, q11);
                    uint32_t pa[4];
                    pa[0] = packh2(p00, p01);
                    pa[1] = packh2(p10, p11);
                    pa[2] = packh2(q00, q01);
                    pa[3] = packh2(q10, q11);
                    uint32_t kcb = g * 32 + ((lane >> 4) & 1) * 16;
                    #pragma unroll
                    for (int db2 = 0; db2 < 4; ++db2) {
                        uint32_t vaddr = vb + swz((uint32_t)((db2 * 16 + (lane & 15)) * 128) + kcb);
                        uint32_t vh[4], vl[4];
                        LDSM4(vh, vaddr);
                        LDSM4(vl, vaddr + 8192);
                        mma_f16(oacc[db2 * 2],     pa, vh[0], vh[2]);
                        mma_f16(oacc[db2 * 2],     pa, vl[0], vl[2]);
                        mma_f16(oacc[db2 * 2 + 1], pa, vh[1], vh[3]);
                        mma_f16(oacc[db2 * 2 + 1], pa, vl[1], vl[3]);
                    }
                }
                __syncthreads();
            }
            #pragma unroll
            for (int db = 0; db < 8; ++db) {
                int col = db * 8 + 2 * (lane & 3);
                *reinterpret_cast<float2*>(out + ((size_t)bh * S + r0g) * Dh + col) =
                    make_float2(oacc[db][0], oacc[db][1]);
                *reinterpret_cast<float2*>(out + ((size_t)bh * S + r0g + 8) * Dh + col) =
                    make_float2(oacc[db][2], oacc[db][3]);
            }
        }
    }
}

extern "C" void kernel_launch(void* const* d_in, const int* in_sizes, int n_in,
                              void* d_out, int out_size) {
    const float* q = (const float*)d_in[0];
    const float* k = (const float*)d_in[1];
    const float* v = (const float*)d_in[2];
    const int* mask = (const int*)d_in[3];

    float* out = (float*)d_out;
    float* p_attn = out + (size_t)Bn * Hn * S * Dh;

    conv_qk<<<NELEM / 4 / THREADS, THREADS>>>(q, k);
    conv_vt<<<dim3(S / 32, Dh / 32, BH), dim3(32, 8)>>>(v);

    cudaFuncSetAttribute(attn_persist, cudaFuncAttributeMaxDynamicSharedMemorySize, SMEM_BYTES);
    attn_persist<<<GRID, THREADS, SMEM_BYTES>>>(mask, out, p_attn);
}

// round 12
// speedup vs baseline: 1.2905x; 1.1503x over previous
#include <cuda_runtime.h>
#include <cuda_bf16.h>
#include <cuda_fp16.h>
#include <cstdint>

namespace {
constexpr int Bn = 4, Hn = 16, S = 2048, Dh = 64;
constexpr int BH = Bn * Hn;
constexpr int MQ = 128;
constexpr int NKA = 128;          // pass A keys per tile
constexpr int NTA = S / NKA;      // 16
constexpr int NK = 64;            // pass B keys per tile
constexpr int NT = S / NK;        // 32
constexpr int THREADS = 256;
constexpr int NELEM = BH * S * Dh;
constexpr float LOG2E = 1.4426950408889634f;
constexpr int NUNITS = BH * (S / MQ);   // 1024 units per pass
constexpr int GRID = 296;               // 2 CTAs/SM x 148 SMs (persistent)

// pass B: K hi [2 buf][8KB] at OFF_K; V hi/lo [2 buf][16KB] at OFF_V
// pass A: K hi 16KB tiles double-buffered at 0 / 16384 (V region unused)
// Q staging (both passes): [0, 32KB)
constexpr int OFF_K   = 0;
constexpr int OFF_V   = 16384;
constexpr int OFF_MS  = 49152;          // 2048 f32
constexpr unsigned SMEM_BYTES = OFF_MS + S * 4;   // 57,344 B
}

__device__ __half g_Qhi[NELEM], g_Qlo[NELEM];
__device__ __half g_Khi[NELEM];
__device__ __half g_VThi[NELEM], g_VTlo[NELEM];   // [bh][d][s]

__device__ unsigned g_ctr;
__device__ unsigned g_flag[NUNITS];
__device__ float    g_linv[NUNITS][MQ];

__device__ __forceinline__ uint32_t s2u(const void* p) {
    uint32_t a;
    asm("{ .reg .u64 t; cvta.to.shared.u64 t, %1; cvt.u32.u64 %0, t; }" : "=r"(a) : "l"(p));
    return a;
}
__device__ __forceinline__ uint32_t swz(uint32_t o) { return o ^ ((o >> 3) & 0x70); }

#define LDSM4(r, a) \
    asm volatile("ldmatrix.sync.aligned.m8n8.x4.shared.b16 {%0,%1,%2,%3},[%4];" \
                 : "=r"((r)[0]), "=r"((r)[1]), "=r"((r)[2]), "=r"((r)[3]) : "r"(a))
#define CP16(dst, src) \
    asm volatile("cp.async.ca.shared.global [%0], [%1], 16;" :: "r"(dst), "l"(src))
#define CP_COMMIT() asm volatile("cp.async.commit_group;" ::: "memory")
#define CP_WAIT0()  asm volatile("cp.async.wait_group 0;" ::: "memory")
#define CP_WAIT1()  asm volatile("cp.async.wait_group 1;" ::: "memory")

__device__ __forceinline__ void mma_f16(float c[4], const uint32_t a[4],
                                        uint32_t b0, uint32_t b1) {
    asm volatile(
        "mma.sync.aligned.m16n8k16.row.col.f32.f16.f16.f32 "
        "{%0,%1,%2,%3},{%4,%5,%6,%7},{%8,%9},{%0,%1,%2,%3};"
        : "+f"(c[0]), "+f"(c[1]), "+f"(c[2]), "+f"(c[3])
        : "r"(a[0]), "r"(a[1]), "r"(a[2]), "r"(a[3]), "r"(b0), "r"(b1));
}

__device__ __forceinline__ float ex2f(float x) {
    float r;
    asm("ex2.approx.ftz.f32 %0, %1;" : "=f"(r) : "f"(x));
    return r;
}
// pack two f32 into f16x2: lo half = x, hi half = y
__device__ __forceinline__ uint32_t packh2(float x, float y) {
    uint32_t r;
    asm("cvt.rn.f16x2.f32 %0, %1, %2;" : "=r"(r) : "f"(y), "f"(x));
    return r;
}

// ---------------- pre-kernels ----------------
__global__ void conv_qk(const float* __restrict__ q, const float* __restrict__ k) {
    // per-launch reset of the persistent-queue state (runs before attn_persist)
    if (blockIdx.x == 0) {
        if (threadIdx.x == 0) g_ctr = 0u;
        for (int i = threadIdx.x; i < NUNITS; i += blockDim.x) g_flag[i] = 0u;
    }
    size_t i4 = (size_t)blockIdx.x * blockDim.x + threadIdx.x;
    size_t e = i4 * 4;
    float4 qv = *reinterpret_cast<const float4*>(q + e);
    float4 kv = *reinterpret_cast<const float4*>(k + e);
    qv.x *= 0.125f; qv.y *= 0.125f; qv.z *= 0.125f; qv.w *= 0.125f;
    // Q: fp16 hi + residual lo
    uint2 wq;
    wq.x = packh2(qv.x, qv.y);
    wq.y = packh2(qv.z, qv.w);
    *reinterpret_cast<uint2*>(g_Qhi + e) = wq;
    float rx = qv.x - __half2float(__ushort_as_half((unsigned short)(wq.x & 0xFFFF)));
    float ry = qv.y - __half2float(__ushort_as_half((unsigned short)(wq.x >> 16)));
    float rz = qv.z - __half2float(__ushort_as_half((unsigned short)(wq.y & 0xFFFF)));
    float rw = qv.w - __half2float(__ushort_as_half((unsigned short)(wq.y >> 16)));
    uint2 wl;
    wl.x = packh2(rx, ry);
    wl.y = packh2(rz, rw);
    *reinterpret_cast<uint2*>(g_Qlo + e) = wl;
    // K: fp16 hi only
    uint2 wk;
    wk.x = packh2(kv.x, kv.y);
    wk.y = packh2(kv.z, kv.w);
    *reinterpret_cast<uint2*>(g_Khi + e) = wk;
}

__global__ void conv_vt(const float* __restrict__ v) {
    __shared__ float t[32][33];
    const int bh = blockIdx.z, s0 = blockIdx.x * 32, d0 = blockIdx.y * 32;
    const int tx = threadIdx.x, ty = threadIdx.y;   // (32, 8)
    #pragma unroll
    for (int j = 0; j < 4; ++j)
        t[ty + 8 * j][tx] = v[((size_t)bh * S + s0 + ty + 8 * j) * Dh + d0 + tx];
    __syncthreads();
    #pragma unroll
    for (int j = 0; j < 4; ++j) {
        float x = t[tx][ty + 8 * j];
        __half h = __float2half_rn(x);
        __half l = __float2half_rn(x - __half2float(h));
        size_t o = ((size_t)bh * Dh + d0 + ty + 8 * j) * S + s0 + tx;
        g_VThi[o] = h; g_VTlo[o] = l;
    }
}

// ---------------- persistent main kernel ----------------
__global__ __launch_bounds__(THREADS, 2)
void attn_persist(const int* __restrict__ mask, float* __restrict__ out,
                  float* __restrict__ p_attn)
{
    extern __shared__ char sm[];
    __shared__ unsigned s_uid;
    const uint32_t sb = s2u(sm);
    const int tid = threadIdx.x;
    const int w = tid >> 5, lane = tid & 31;
    float* msf = reinterpret_cast<float*>(sm + OFF_MS);

    for (;;) {
        __syncthreads();   // previous unit fully done with smem + s_uid
        if (tid == 0) s_uid = atomicAdd(&g_ctr, 1u);
        __syncthreads();
        const unsigned uid = s_uid;
        if (uid >= 2u * NUNITS) break;
        const bool isA = uid < (unsigned)NUNITS;
        const int u  = isA ? (int)uid : (int)(uid - NUNITS);
        const int qt = u & 15, bh = u >> 4;
        const int b  = bh >> 4;
        const int q0 = qt * MQ;

        // mask row for this batch
        for (int i = tid; i < S; i += THREADS)
            msf[i] = (mask[b * S + i] != 0) ? 1.0f : 0.0f;

        if (isA) {
            // ======== PASS A UNIT: rowsums (1-term fp16 qh*kh) ========
            #pragma unroll
            for (int i = 0; i < 4; ++i) {   // stage Q-hi (16KB at base 0)
                int fi = tid + i * THREADS;
                int row = fi >> 3, c8 = fi & 7;
                CP16(sb + swz((uint32_t)(row * 128 + c8 * 16)),
                     g_Qhi + ((size_t)bh * S + q0 + row) * Dh + c8 * 8);
            }
            CP_COMMIT(); CP_WAIT0(); __syncthreads();
            uint32_t qa0[4][4];
            #pragma unroll
            for (int ks = 0; ks < 4; ++ks) {
                uint32_t a = sb +
                    swz((uint32_t)((w * 16 + (lane & 15)) * 128 + ks * 32 +
                                   ((lane >> 4) & 1) * 16));
                LDSM4(qa0[ks], a);
            }
            __syncthreads();

            float rs0 = 0.f, rs1 = 0.f;
            #pragma unroll
            for (int i = 0; i < 4; ++i) {   // preload K tile 0 (16KB, buffers at 0/16384)
                int fi = tid + i * THREADS;
                int row = fi >> 3, c8 = fi & 7;
                CP16(sb + swz((uint32_t)(row * 128 + c8 * 16)),
                     g_Khi + ((size_t)bh * S + row) * Dh + c8 * 8);
            }
            CP_COMMIT();
            for (int t = 0; t < NTA; ++t) {
                const int t0 = t * NKA;
                if (t + 1 < NTA) {
                    const uint32_t dstb = sb + ((t + 1) & 1) * 16384;
                    #pragma unroll
                    for (int i = 0; i < 4; ++i) {
                        int fi = tid + i * THREADS;
                        int row = fi >> 3, c8 = fi & 7;
                        CP16(dstb + swz((uint32_t)(row * 128 + c8 * 16)),
                             g_Khi + ((size_t)bh * S + t0 + NKA + row) * Dh + c8 * 8);
                    }
                    CP_COMMIT(); CP_WAIT1();
                } else {
                    CP_WAIT0();
                }
                __syncthreads();
                const uint32_t kbase = sb + (t & 1) * 16384;
                #pragma unroll
                for (int g = 0; g < 8; ++g) {
                    float c0[4] = {0.f, 0.f, 0.f, 0.f};
                    float c1[4] = {0.f, 0.f, 0.f, 0.f};
                    uint32_t rowb = g * 16 + (lane & 15);
                    #pragma unroll
                    for (int ks = 0; ks < 4; ++ks) {
                        uint32_t kh[4];
                        LDSM4(kh, kbase + swz(rowb * 128 + ks * 32 + ((lane >> 4) & 1) * 16));
                        mma_f16(c0, qa0[ks], kh[0], kh[2]);
                        mma_f16(c1, qa0[ks], kh[1], kh[3]);
                    }
                    int colA = t0 + g * 16 + 2 * (lane & 3);
                    float2 mA = *reinterpret_cast<const float2*>(msf + colA);
                    float2 mB = *reinterpret_cast<const float2*>(msf + colA + 8);
                    rs0 += mA.x * ex2f(c0[0] * LOG2E) + mA.y * ex2f(c0[1] * LOG2E);
                    rs1 += mA.x * ex2f(c0[2] * LOG2E) + mA.y * ex2f(c0[3] * LOG2E);
                    rs0 += mB.x * ex2f(c1[0] * LOG2E) + mB.y * ex2f(c1[1] * LOG2E);
                    rs1 += mB.x * ex2f(c1[2] * LOG2E) + mB.y * ex2f(c1[3] * LOG2E);
                }
                __syncthreads();
            }
            rs0 += __shfl_xor_sync(0xffffffffu, rs0, 1);
            rs0 += __shfl_xor_sync(0xffffffffu, rs0, 2);
            rs1 += __shfl_xor_sync(0xffffffffu, rs1, 1);
            rs1 += __shfl_xor_sync(0xffffffffu, rs1, 2);
            if ((lane & 3) == 0) {
                g_linv[u][w * 16 + (lane >> 2)]     = -__log2f(rs0);
                g_linv[u][w * 16 + 8 + (lane >> 2)] = -__log2f(rs1);
            }
            __syncthreads();
            __threadfence();                       // release: linv visible before flag
            if (tid == 0) atomicExch(&g_flag[u], 1u);
        } else {
            // ======== PASS B UNIT: p_attn + out (2-term fp16 QK, 2-MMA fp16 PV) ========
            #pragma unroll
            for (int buf = 0; buf < 2; ++buf) {    // stage Q hi/lo at 0 / 16384
                const __half* src = buf ? g_Qlo : g_Qhi;
                #pragma unroll
                for (int i = 0; i < 4; ++i) {
                    int fi = tid + i * THREADS;
                    int row = fi >> 3, c8 = fi & 7;
                    CP16(sb + buf * 16384 + swz((uint32_t)(row * 128 + c8 * 16)),
                         src + ((size_t)bh * S + q0 + row) * Dh + c8 * 8);
                }
            }
            CP_COMMIT(); CP_WAIT0(); __syncthreads();
            uint32_t qa[2][4][4];
            #pragma unroll
            for (int buf = 0; buf < 2; ++buf)
                #pragma unroll
                for (int ks = 0; ks < 4; ++ks) {
                    uint32_t a = sb + buf * 16384 +
                        swz((uint32_t)((w * 16 + (lane & 15)) * 128 + ks * 32 +
                                       ((lane >> 4) & 1) * 16));
                    LDSM4(qa[buf][ks], a);
                }
            // acquire rowsums from the matching A unit
            if (tid == 0) {
                while (atomicAdd(&g_flag[u], 0u) == 0u) __nanosleep(200);
                __threadfence();
            }
            __syncthreads();
            const float linv0 = __ldcg(&g_linv[u][w * 16 + (lane >> 2)]);
            const float linv1 = __ldcg(&g_linv[u][w * 16 + 8 + (lane >> 2)]);

            float oacc[8][4];
            #pragma unroll
            for (int d = 0; d < 8; ++d)
                #pragma unroll
                for (int e = 0; e < 4; ++e) oacc[d][e] = 0.f;

            const int r0g = q0 + w * 16 + (lane >> 2);
            float* pa_row0 = p_attn + ((size_t)bh * S + r0g) * S;
            float* pa_row1 = p_attn + ((size_t)bh * S + r0g + 8) * S;

            auto loadB = [&](int t, int buf) {
                const int t0 = t * NK;
                const uint32_t kbuf = sb + OFF_K + buf * 8192;
                const uint32_t vbuf = sb + OFF_V + buf * 16384;
                // K hi only: 8KB = 512 chunks
                #pragma unroll
                for (int i = 0; i < 2; ++i) {
                    int fi = tid + i * THREADS;
                    int row = fi >> 3, c8 = fi & 7;
                    CP16(kbuf + swz((uint32_t)(row * 128 + c8 * 16)),
                         g_Khi + ((size_t)bh * S + t0 + row) * Dh + c8 * 8);
                }
                // V hi + lo
                #pragma unroll
                for (int hilo = 0; hilo < 2; ++hilo) {
                    const __half* vsrc = hilo ? g_VTlo : g_VThi;
                    #pragma unroll
                    for (int i = 0; i < 2; ++i) {
                        int fi = tid + i * THREADS;
                        int row = fi >> 3, c8 = fi & 7;
                        CP16(vbuf + hilo * 8192 + swz((uint32_t)(row * 128 + c8 * 16)),
                             vsrc + ((size_t)bh * Dh + row) * S + t0 + c8 * 8);
                    }
                }
            };

            __syncthreads();   // Q staging reads done before K tiles overwrite
            loadB(0, 0); CP_COMMIT();
            for (int t = 0; t < NT; ++t) {
                const int t0 = t * NK;
                if (t + 1 < NT) { loadB(t + 1, (t + 1) & 1); CP_COMMIT(); CP_WAIT1(); }
                else            { CP_WAIT0(); }
                __syncthreads();
                const uint32_t kb = sb + OFF_K + (t & 1) * 8192;
                const uint32_t vb = sb + OFF_V + (t & 1) * 16384;

                #pragma unroll
                for (int g = 0; g < 4; ++g) {
                    float c0[4] = {0.f, 0.f, 0.f, 0.f};
                    float c1[4] = {0.f, 0.f, 0.f, 0.f};
                    uint32_t rowb = g * 16 + (lane & 15);
                    #pragma unroll
                    for (int ks = 0; ks < 4; ++ks) {
                        uint32_t kh[4];
                        LDSM4(kh, kb + swz(rowb * 128 + ks * 32 + ((lane >> 4) & 1) * 16));
                        mma_f16(c0, qa[0][ks], kh[0], kh[2]);
                        mma_f16(c0, qa[1][ks], kh[0], kh[2]);
                        mma_f16(c1, qa[0][ks], kh[1], kh[3]);
                        mma_f16(c1, qa[1][ks], kh[1], kh[3]);
                    }
                    int colA = t0 + g * 16 + 2 * (lane & 3);
                    float2 mA = *reinterpret_cast<const float2*>(msf + colA);
                    float2 mB = *reinterpret_cast<const float2*>(msf + colA + 8);
                    float p00 = mA.x * ex2f(fmaf(c0[0], LOG2E, linv0));
                    float p01 = mA.y * ex2f(fmaf(c0[1], LOG2E, linv0));
                    float p10 = mA.x * ex2f(fmaf(c0[2], LOG2E, linv1));
                    float p11 = mA.y * ex2f(fmaf(c0[3], LOG2E, linv1));
                    float q00 = mB.x * ex2f(fmaf(c1[0], LOG2E, linv0));
                    float q01 = mB.y * ex2f(fmaf(c1[1], LOG2E, linv0));
                    float q10 = mB.x * ex2f(fmaf(c1[2], LOG2E, linv1));
                    float q11 = mB.y * ex2f(fmaf(c1[3], LOG2E, linv1));
                    *reinterpret_cast<float2*>(pa_row0 + colA)     = make_float2(p00, p01);
                    *reinterpret_cast<float2*>(pa_row0 + colA + 8) = make_float2(q00, q01);
                    *reinterpret_cast<float2*>(pa_row1 + colA)     = make_float2(p10, p11);
                    *reinterpret_cast<float2*>(pa_row1 + colA + 8) = make_float2(q10, q11);
                    uint32_t pa[4];
                    pa[0] = packh2(p00, p01);
                    pa[1] = packh2(p10, p11);
                    pa[2] = packh2(q00, q01);
                    pa[3] = packh2(q10, q11);
                    uint32_t kcb = g * 32 + ((lane >> 4) & 1) * 16;
                    #pragma unroll
                    for (int db2 = 0; db2 < 4; ++db2) {
                        uint32_t vaddr = vb + swz((uint32_t)((db2 * 16 + (lane & 15)) * 128) + kcb);
                        uint32_t vh[4], vl[4];
                        LDSM4(vh, vaddr);
                        LDSM4(vl, vaddr + 8192);
                        mma_f16(oacc[db2 * 2],     pa, vh[0], vh[2]);
                        mma_f16(oacc[db2 * 2],     pa, vl[0], vl[2]);
                        mma_f16(oacc[db2 * 2 + 1], pa, vh[1], vh[3]);
                        mma_f16(oacc[db2 * 2 + 1], pa, vl[1], vl[3]);
                    }
                }
                __syncthreads();
            }
            #pragma unroll
            for (int db = 0; db < 8; ++db) {
                int col = db * 8 + 2 * (lane & 3);
                *reinterpret_cast<float2*>(out + ((size_t)bh * S + r0g) * Dh + col) =
                    make_float2(oacc[db][0], oacc[db][1]);
                *reinterpret_cast<float2*>(out + ((size_t)bh * S + r0g + 8) * Dh + col) =
                    make_float2(oacc[db][2], oacc[db][3]);
            }
        }
    }
}

extern "C" void kernel_launch(void* const* d_in, const int* in_sizes, int n_in,
                              void* d_out, int out_size) {
    const float* q = (const float*)d_in[0];
    const float* k = (const float*)d_in[1];
    const float* v = (const float*)d_in[2];
    const int* mask = (const int*)d_in[3];

    float* out = (float*)d_out;
    float* p_attn = out + (size_t)Bn * Hn * S * Dh;

    conv_qk<<<NELEM / 4 / THREADS, THREADS>>>(q, k);
    conv_vt<<<dim3(S / 32, Dh / 32, BH), dim3(32, 8)>>>(v);

    cudaFuncSetAttribute(attn_persist, cudaFuncAttributeMaxDynamicSharedMemorySize, SMEM_BYTES);
    attn_persist<<<GRID, THREADS, SMEM_BYTES>>>(mask, out, p_attn);
}

// round 14
// speedup vs baseline: 1.6040x; 1.2429x over previous
#include <cuda_runtime.h>
#include <cuda_fp16.h>
#include <cstdint>

namespace {
constexpr int Bn = 4, Hn = 16, S = 2048, Dh = 64;
constexpr int BH = Bn * Hn;
constexpr int MQ = 128;
constexpr int NKA = 128;          // pass A keys per tile
constexpr int NTA = S / NKA;      // 16
constexpr int NK = 64;            // pass B keys per tile
constexpr int NT = S / NK;        // 32
constexpr int THREADS = 256;
constexpr int NELEM = BH * S * Dh;
constexpr float LOG2E = 1.4426950408889634f;
constexpr int NUNITS = BH * (S / MQ);   // 1024 units per pass
constexpr int GRID = 296;               // 2 CTAs/SM x 148 SMs (persistent)

// pass B: K hi [2 buf][8KB] at 0; V hi [2 buf][8KB] at 16384
// pass A: K hi 16KB tiles double-buffered at 0 / 16384
// Q staging (both passes): [0, 16KB)
constexpr int OFF_V   = 16384;
constexpr int OFF_MS  = 32768;          // 2048 f32
constexpr unsigned SMEM_BYTES = OFF_MS + S * 4;   // 40,960 B
}

__device__ __half g_Qhi[NELEM];
__device__ __half g_Khi[NELEM];
__device__ __half g_VThi[NELEM];   // [bh][d][s]

__device__ unsigned g_ctr;
__device__ unsigned g_flag[NUNITS];
__device__ float    g_linv[NUNITS][MQ];

__device__ __forceinline__ uint32_t s2u(const void* p) {
    uint32_t a;
    asm("{ .reg .u64 t; cvta.to.shared.u64 t, %1; cvt.u32.u64 %0, t; }" : "=r"(a) : "l"(p));
    return a;
}
__device__ __forceinline__ uint32_t swz(uint32_t o) { return o ^ ((o >> 3) & 0x70); }

#define LDSM4(r, a) \
    asm volatile("ldmatrix.sync.aligned.m8n8.x4.shared.b16 {%0,%1,%2,%3},[%4];" \
                 : "=r"((r)[0]), "=r"((r)[1]), "=r"((r)[2]), "=r"((r)[3]) : "r"(a))
#define CP16(dst, src) \
    asm volatile("cp.async.ca.shared.global [%0], [%1], 16;" :: "r"(dst), "l"(src))
#define CP_COMMIT() asm volatile("cp.async.commit_group;" ::: "memory")
#define CP_WAIT0()  asm volatile("cp.async.wait_group 0;" ::: "memory")
#define CP_WAIT1()  asm volatile("cp.async.wait_group 1;" ::: "memory")

__device__ __forceinline__ void mma_f16(float c[4], const uint32_t a[4],
                                        uint32_t b0, uint32_t b1) {
    asm volatile(
        "mma.sync.aligned.m16n8k16.row.col.f32.f16.f16.f32 "
        "{%0,%1,%2,%3},{%4,%5,%6,%7},{%8,%9},{%0,%1,%2,%3};"
        : "+f"(c[0]), "+f"(c[1]), "+f"(c[2]), "+f"(c[3])
        : "r"(a[0]), "r"(a[1]), "r"(a[2]), "r"(a[3]), "r"(b0), "r"(b1));
}

__device__ __forceinline__ float ex2f(float x) {
    float r;
    asm("ex2.approx.ftz.f32 %0, %1;" : "=f"(r) : "f"(x));
    return r;
}
// pack two f32 into f16x2: lo half = x, hi half = y
__device__ __forceinline__ uint32_t packh2(float x, float y) {
    uint32_t r;
    asm("cvt.rn.f16x2.f32 %0, %1, %2;" : "=r"(r) : "f"(y), "f"(x));
    return r;
}

// ---------------- pre-kernels ----------------
__global__ void conv_qk(const float* __restrict__ q, const float* __restrict__ k) {
    // per-launch reset of the persistent-queue state (runs before attn_persist)
    if (blockIdx.x == 0) {
        if (threadIdx.x == 0) g_ctr = 0u;
        for (int i = threadIdx.x; i < NUNITS; i += blockDim.x) g_flag[i] = 0u;
    }
    size_t i4 = (size_t)blockIdx.x * blockDim.x + threadIdx.x;
    size_t e = i4 * 4;
    float4 qv = *reinterpret_cast<const float4*>(q + e);
    float4 kv = *reinterpret_cast<const float4*>(k + e);
    qv.x *= 0.125f; qv.y *= 0.125f; qv.z *= 0.125f; qv.w *= 0.125f;
    uint2 wq;
    wq.x = packh2(qv.x, qv.y);
    wq.y = packh2(qv.z, qv.w);
    *reinterpret_cast<uint2*>(g_Qhi + e) = wq;
    uint2 wk;
    wk.x = packh2(kv.x, kv.y);
    wk.y = packh2(kv.z, kv.w);
    *reinterpret_cast<uint2*>(g_Khi + e) = wk;
}

__global__ void conv_vt(const float* __restrict__ v) {
    __shared__ float t[32][33];
    const int bh = blockIdx.z, s0 = blockIdx.x * 32, d0 = blockIdx.y * 32;
    const int tx = threadIdx.x, ty = threadIdx.y;   // (32, 8)
    #pragma unroll
    for (int j = 0; j < 4; ++j)
        t[ty + 8 * j][tx] = v[((size_t)bh * S + s0 + ty + 8 * j) * Dh + d0 + tx];
    __syncthreads();
    #pragma unroll
    for (int j = 0; j < 4; ++j) {
        float x = t[tx][ty + 8 * j];
        size_t o = ((size_t)bh * Dh + d0 + ty + 8 * j) * S + s0 + tx;
        g_VThi[o] = __float2half_rn(x);
    }
}

// ---------------- persistent main kernel ----------------
__global__ __launch_bounds__(THREADS, 2)
void attn_persist(const int* __restrict__ mask, float* __restrict__ out,
                  float* __restrict__ p_attn)
{
    extern __shared__ char sm[];
    __shared__ unsigned s_uid;
    const uint32_t sb = s2u(sm);
    const int tid = threadIdx.x;
    const int w = tid >> 5, lane = tid & 31;
    float* msf = reinterpret_cast<float*>(sm + OFF_MS);

    for (;;) {
        __syncthreads();   // previous unit fully done with smem + s_uid
        if (tid == 0) s_uid = atomicAdd(&g_ctr, 1u);
        __syncthreads();
        const unsigned uid = s_uid;
        if (uid >= 2u * NUNITS) break;
        const bool isA = uid < (unsigned)NUNITS;
        const int u  = isA ? (int)uid : (int)(uid - NUNITS);
        const int qt = u & 15, bh = u >> 4;
        const int b  = bh >> 4;
        const int q0 = qt * MQ;

        // mask row for this batch
        for (int i = tid; i < S; i += THREADS)
            msf[i] = (mask[b * S + i] != 0) ? 1.0f : 0.0f;

        // ---- stage Q-hi (16KB at base 0) and load A-fragments (both passes) ----
        #pragma unroll
        for (int i = 0; i < 4; ++i) {
            int fi = tid + i * THREADS;
            int row = fi >> 3, c8 = fi & 7;
            CP16(sb + swz((uint32_t)(row * 128 + c8 * 16)),
                 g_Qhi + ((size_t)bh * S + q0 + row) * Dh + c8 * 8);
        }
        CP_COMMIT(); CP_WAIT0(); __syncthreads();
        uint32_t qa[4][4];
        #pragma unroll
        for (int ks = 0; ks < 4; ++ks) {
            uint32_t a = sb +
                swz((uint32_t)((w * 16 + (lane & 15)) * 128 + ks * 32 +
                               ((lane >> 4) & 1) * 16));
            LDSM4(qa[ks], a);
        }
        __syncthreads();   // Q staging reads done; smem free for K/V tiles

        if (isA) {
            // ======== PASS A UNIT: rowsums (1-term fp16 qh*kh) ========
            float rs0 = 0.f, rs1 = 0.f;
            #pragma unroll
            for (int i = 0; i < 4; ++i) {   // preload K tile 0 (16KB, buffers at 0/16384)
                int fi = tid + i * THREADS;
                int row = fi >> 3, c8 = fi & 7;
                CP16(sb + swz((uint32_t)(row * 128 + c8 * 16)),
                     g_Khi + ((size_t)bh * S + row) * Dh + c8 * 8);
            }
            CP_COMMIT();
            for (int t = 0; t < NTA; ++t) {
                const int t0 = t * NKA;
                if (t + 1 < NTA) {
                    const uint32_t dstb = sb + ((t + 1) & 1) * 16384;
                    #pragma unroll
                    for (int i = 0; i < 4; ++i) {
                        int fi = tid + i * THREADS;
                        int row = fi >> 3, c8 = fi & 7;
                        CP16(dstb + swz((uint32_t)(row * 128 + c8 * 16)),
                             g_Khi + ((size_t)bh * S + t0 + NKA + row) * Dh + c8 * 8);
                    }
                    CP_COMMIT(); CP_WAIT1();
                } else {
                    CP_WAIT0();
                }
                __syncthreads();
                const uint32_t kbase = sb + (t & 1) * 16384;
                #pragma unroll
                for (int g = 0; g < 8; ++g) {
                    float c0[4] = {0.f, 0.f, 0.f, 0.f};
                    float c1[4] = {0.f, 0.f, 0.f, 0.f};
                    uint32_t rowb = g * 16 + (lane & 15);
                    #pragma unroll
                    for (int ks = 0; ks < 4; ++ks) {
                        uint32_t kh[4];
                        LDSM4(kh, kbase + swz(rowb * 128 + ks * 32 + ((lane >> 4) & 1) * 16));
                        mma_f16(c0, qa[ks], kh[0], kh[2]);
                        mma_f16(c1, qa[ks], kh[1], kh[3]);
                    }
                    int colA = t0 + g * 16 + 2 * (lane & 3);
                    float2 mA = *reinterpret_cast<const float2*>(msf + colA);
                    float2 mB = *reinterpret_cast<const float2*>(msf + colA + 8);
                    rs0 += mA.x * ex2f(c0[0] * LOG2E) + mA.y * ex2f(c0[1] * LOG2E);
                    rs1 += mA.x * ex2f(c0[2] * LOG2E) + mA.y * ex2f(c0[3] * LOG2E);
                    rs0 += mB.x * ex2f(c1[0] * LOG2E) + mB.y * ex2f(c1[1] * LOG2E);
                    rs1 += mB.x * ex2f(c1[2] * LOG2E) + mB.y * ex2f(c1[3] * LOG2E);
                }
                __syncthreads();
            }
            rs0 += __shfl_xor_sync(0xffffffffu, rs0, 1);
            rs0 += __shfl_xor_sync(0xffffffffu, rs0, 2);
            rs1 += __shfl_xor_sync(0xffffffffu, rs1, 1);
            rs1 += __shfl_xor_sync(0xffffffffu, rs1, 2);
            if ((lane & 3) == 0) {
                g_linv[u][w * 16 + (lane >> 2)]     = -__log2f(rs0);
                g_linv[u][w * 16 + 8 + (lane >> 2)] = -__log2f(rs1);
            }
            __syncthreads();
            __threadfence();                       // release: linv visible before flag
            if (tid == 0) atomicExch(&g_flag[u], 1u);
        } else {
            // ======== PASS B UNIT: p_attn + out (1-term fp16 QK, single-V PV) ========
            // acquire rowsums from the matching A unit
            if (tid == 0) {
                while (atomicAdd(&g_flag[u], 0u) == 0u) __nanosleep(200);
                __threadfence();
            }
            __syncthreads();
            const float linv0 = __ldcg(&g_linv[u][w * 16 + (lane >> 2)]);
            const float linv1 = __ldcg(&g_linv[u][w * 16 + 8 + (lane >> 2)]);

            float oacc[8][4];
            #pragma unroll
            for (int d = 0; d < 8; ++d)
                #pragma unroll
                for (int e = 0; e < 4; ++e) oacc[d][e] = 0.f;

            const int r0g = q0 + w * 16 + (lane >> 2);
            float* pa_row0 = p_attn + ((size_t)bh * S + r0g) * S;
            float* pa_row1 = p_attn + ((size_t)bh * S + r0g + 8) * S;

            auto loadB = [&](int t, int buf) {
                const int t0 = t * NK;
                const uint32_t kbuf = sb + buf * 8192;
                const uint32_t vbuf = sb + OFF_V + buf * 8192;
                #pragma unroll
                for (int i = 0; i < 2; ++i) {
                    int fi = tid + i * THREADS;
                    int row = fi >> 3, c8 = fi & 7;
                    uint32_t soff = swz((uint32_t)(row * 128 + c8 * 16));
                    CP16(kbuf + soff,
                         g_Khi + ((size_t)bh * S + t0 + row) * Dh + c8 * 8);
                    CP16(vbuf + soff,
                         g_VThi + ((size_t)bh * Dh + row) * S + t0 + c8 * 8);
                }
            };

            loadB(0, 0); CP_COMMIT();
            for (int t = 0; t < NT; ++t) {
                const int t0 = t * NK;
                if (t + 1 < NT) { loadB(t + 1, (t + 1) & 1); CP_COMMIT(); CP_WAIT1(); }
                else            { CP_WAIT0(); }
                __syncthreads();
                const uint32_t kb = sb + (t & 1) * 8192;
                const uint32_t vb = sb + OFF_V + (t & 1) * 8192;

                #pragma unroll
                for (int g = 0; g < 4; ++g) {
                    float c0[4] = {0.f, 0.f, 0.f, 0.f};
                    float c1[4] = {0.f, 0.f, 0.f, 0.f};
                    uint32_t rowb = g * 16 + (lane & 15);
                    #pragma unroll
                    for (int ks = 0; ks < 4; ++ks) {
                        uint32_t kh[4];
                        LDSM4(kh, kb + swz(rowb * 128 + ks * 32 + ((lane >> 4) & 1) * 16));
                        mma_f16(c0, qa[ks], kh[0], kh[2]);
                        mma_f16(c1, qa[ks], kh[1], kh[3]);
                    }
                    int colA = t0 + g * 16 + 2 * (lane & 3);
                    float2 mA = *reinterpret_cast<const float2*>(msf + colA);
                    float2 mB = *reinterpret_cast<const float2*>(msf + colA + 8);
                    float p00 = mA.x * ex2f(fmaf(c0[0], LOG2E, linv0));
                    float p01 = mA.y * ex2f(fmaf(c0[1], LOG2E, linv0));
                    float p10 = mA.x * ex2f(fmaf(c0[2], LOG2E, linv1));
                    float p11 = mA.y * ex2f(fmaf(c0[3], LOG2E, linv1));
                    float q00 = mB.x * ex2f(fmaf(c1[0], LOG2E, linv0));
                    float q01 = mB.y * ex2f(fmaf(c1[1], LOG2E, linv0));
                    float q10 = mB.x * ex2f(fmaf(c1[2], LOG2E, linv1));
                    float q11 = mB.y * ex2f(fmaf(c1[3], LOG2E, linv1));
                    *reinterpret_cast<float2*>(pa_row0 + colA)     = make_float2(p00, p01);
                    *reinterpret_cast<float2*>(pa_row0 + colA + 8) = make_float2(q00, q01);
                    *reinterpret_cast<float2*>(pa_row1 + colA)     = make_float2(p10, p11);
                    *reinterpret_cast<float2*>(pa_row1 + colA + 8) = make_float2(q10, q11);
                    uint32_t pa[4];
                    pa[0] = packh2(p00, p01);
                    pa[1] = packh2(p10, p11);
                    pa[2] = packh2(q00, q01);
                    pa[3] = packh2(q10, q11);
                    uint32_t kcb = g * 32 + ((lane >> 4) & 1) * 16;
                    #pragma unroll
                    for (int db2 = 0; db2 < 4; ++db2) {
                        uint32_t vh[4];
                        LDSM4(vh, vb + swz((uint32_t)((db2 * 16 + (lane & 15)) * 128) + kcb));
                        mma_f16(oacc[db2 * 2],     pa, vh[0], vh[2]);
                        mma_f16(oacc[db2 * 2 + 1], pa, vh[1], vh[3]);
                    }
                }
                __syncthreads();
            }
            #pragma unroll
            for (int db = 0; db < 8; ++db) {
                int col = db * 8 + 2 * (lane & 3);
                *reinterpret_cast<float2*>(out + ((size_t)bh * S + r0g) * Dh + col) =
                    make_float2(oacc[db][0], oacc[db][1]);
                *reinterpret_cast<float2*>(out + ((size_t)bh * S + r0g + 8) * Dh + col) =
                    make_float2(oacc[db][2], oacc[db][3]);
            }
        }
    }
}

extern "C" void kernel_launch(void* const* d_in, const int* in_sizes, int n_in,
                              void* d_out, int out_size) {
    const float* q = (const float*)d_in[0];
    const float* k = (const float*)d_in[1];
    const float* v = (const float*)d_in[2];
    const int* mask = (const int*)d_in[3];

    float* out = (float*)d_out;
    float* p_attn = out + (size_t)Bn * Hn * S * Dh;

    conv_qk<<<NELEM / 4 / THREADS, THREADS>>>(q, k);
    conv_vt<<<dim3(S / 32, Dh / 32, BH), dim3(32, 8)>>>(v);

    cudaFuncSetAttribute(attn_persist, cudaFuncAttributeMaxDynamicSharedMemorySize, SMEM_BYTES);
    attn_persist<<<GRID, THREADS, SMEM_BYTES>>>(mask, out, p_attn);
}

// round 15
// speedup vs baseline: 1.6112x; 1.0045x over previous
#include <cuda_runtime.h>
#include <cuda_fp16.h>
#include <cstdint>

namespace {
constexpr int Bn = 4, Hn = 16, S = 2048, Dh = 64;
constexpr int BH = Bn * Hn;
constexpr int MQ = 128;
constexpr int NKA = 128;          // pass A keys per tile
constexpr int NTA = S / NKA;      // 16
constexpr int NK = 64;            // pass B keys per tile
constexpr int NT = S / NK;        // 32
constexpr int THREADS = 256;
constexpr int NELEM = BH * S * Dh;
constexpr float LOG2E = 1.4426950408889634f;
constexpr int NUNITS = BH * (S / MQ);   // 1024 units per pass
constexpr int GRID = 296;               // 2 CTAs/SM x 148 SMs (persistent)
constexpr int QK_BLOCKS = NELEM / 4 / THREADS;            // 8192
constexpr int VT_BLOCKS = (S / 32) * (Dh / 32) * BH;      // 8192

// pass B: K hi [2 buf][8KB] at 0; V hi [2 buf][8KB] at 16384
// pass A: K hi 16KB tiles double-buffered at 0 / 16384
// Q staging (both passes): [0, 16KB)
constexpr int OFF_V   = 16384;
constexpr int OFF_MS  = 32768;          // 2048 f32 (log-domain mask)
constexpr unsigned SMEM_BYTES = OFF_MS + S * 4;   // 40,960 B
}

__device__ __half g_Qhi[NELEM];
__device__ __half g_Khi[NELEM];
__device__ __half g_VThi[NELEM];   // [bh][d][s]

__device__ unsigned g_ctr;
__device__ unsigned g_flag[NUNITS];
__device__ float    g_linv[NUNITS][MQ];

__device__ __forceinline__ uint32_t s2u(const void* p) {
    uint32_t a;
    asm("{ .reg .u64 t; cvta.to.shared.u64 t, %1; cvt.u32.u64 %0, t; }" : "=r"(a) : "l"(p));
    return a;
}
__device__ __forceinline__ uint32_t swz(uint32_t o) { return o ^ ((o >> 3) & 0x70); }

#define LDSM4(r, a) \
    asm volatile("ldmatrix.sync.aligned.m8n8.x4.shared.b16 {%0,%1,%2,%3},[%4];" \
                 : "=r"((r)[0]), "=r"((r)[1]), "=r"((r)[2]), "=r"((r)[3]) : "r"(a))
#define CP16(dst, src) \
    asm volatile("cp.async.ca.shared.global [%0], [%1], 16;" :: "r"(dst), "l"(src))
#define CP_COMMIT() asm volatile("cp.async.commit_group;" ::: "memory")
#define CP_WAIT0()  asm volatile("cp.async.wait_group 0;" ::: "memory")
#define CP_WAIT1()  asm volatile("cp.async.wait_group 1;" ::: "memory")

__device__ __forceinline__ void mma_f16(float c[4], const uint32_t a[4],
                                        uint32_t b0, uint32_t b1) {
    asm volatile(
        "mma.sync.aligned.m16n8k16.row.col.f32.f16.f16.f32 "
        "{%0,%1,%2,%3},{%4,%5,%6,%7},{%8,%9},{%0,%1,%2,%3};"
        : "+f"(c[0]), "+f"(c[1]), "+f"(c[2]), "+f"(c[3])
        : "r"(a[0]), "r"(a[1]), "r"(a[2]), "r"(a[3]), "r"(b0), "r"(b1));
}

__device__ __forceinline__ float ex2f(float x) {
    float r;
    asm("ex2.approx.ftz.f32 %0, %1;" : "=f"(r) : "f"(x));
    return r;
}
// pack two f32 into f16x2: lo half = x, hi half = y
__device__ __forceinline__ uint32_t packh2(float x, float y) {
    uint32_t r;
    asm("cvt.rn.f16x2.f32 %0, %1, %2;" : "=r"(r) : "f"(y), "f"(x));
    return r;
}

// ---------------- fused pre-kernel: QK convert + V transpose ----------------
__global__ void conv_all(const float* __restrict__ q, const float* __restrict__ k,
                         const float* __restrict__ v) {
    __shared__ float t[32][33];
    const int bid = blockIdx.x;
    if (bid < QK_BLOCKS) {
        // per-launch reset of the persistent-queue state
        if (bid == 0) {
            if (threadIdx.x == 0) g_ctr = 0u;
            for (int i = threadIdx.x; i < NUNITS; i += blockDim.x) g_flag[i] = 0u;
        }
        size_t i4 = (size_t)bid * blockDim.x + threadIdx.x;
        size_t e = i4 * 4;
        float4 qv = *reinterpret_cast<const float4*>(q + e);
        float4 kv = *reinterpret_cast<const float4*>(k + e);
        qv.x *= 0.125f; qv.y *= 0.125f; qv.z *= 0.125f; qv.w *= 0.125f;
        uint2 wq;
        wq.x = packh2(qv.x, qv.y);
        wq.y = packh2(qv.z, qv.w);
        *reinterpret_cast<uint2*>(g_Qhi + e) = wq;
        uint2 wk;
        wk.x = packh2(kv.x, kv.y);
        wk.y = packh2(kv.z, kv.w);
        *reinterpret_cast<uint2*>(g_Khi + e) = wk;
    } else {
        const int vb = bid - QK_BLOCKS;
        const int bh = vb >> 7;            // 128 blocks per bh
        const int rem = vb & 127;
        const int s0 = (rem >> 1) << 5;
        const int d0 = (rem & 1) << 5;
        const int tx = threadIdx.x & 31, ty = threadIdx.x >> 5;   // (32, 8)
        #pragma unroll
        for (int j = 0; j < 4; ++j)
            t[ty + 8 * j][tx] = v[((size_t)bh * S + s0 + ty + 8 * j) * Dh + d0 + tx];
        __syncthreads();
        #pragma unroll
        for (int j = 0; j < 4; ++j) {
            float x = t[tx][ty + 8 * j];
            size_t o = ((size_t)bh * Dh + d0 + ty + 8 * j) * S + s0 + tx;
            g_VThi[o] = __float2half_rn(x);
        }
    }
}

// ---------------- persistent main kernel ----------------
__global__ __launch_bounds__(THREADS, 2)
void attn_persist(const int* __restrict__ mask, float* __restrict__ out,
                  float* __restrict__ p_attn)
{
    extern __shared__ char sm[];
    __shared__ unsigned s_uid;
    const uint32_t sb = s2u(sm);
    const int tid = threadIdx.x;
    const int w = tid >> 5, lane = tid & 31;
    float* msf = reinterpret_cast<float*>(sm + OFF_MS);

    for (;;) {
        __syncthreads();   // previous unit fully done with smem + s_uid
        if (tid == 0) s_uid = atomicAdd(&g_ctr, 1u);
        __syncthreads();
        const unsigned uid = s_uid;
        if (uid >= 2u * NUNITS) break;
        const bool isA = uid < (unsigned)NUNITS;
        const int u  = isA ? (int)uid : (int)(uid - NUNITS);
        const int qt = u & 15, bh = u >> 4;
        const int b  = bh >> 4;
        const int q0 = qt * MQ;

        // log-domain mask row: 0 (keep) or -1e30 (kill via ex2 underflow)
        for (int i = tid; i < S; i += THREADS)
            msf[i] = (mask[b * S + i] != 0) ? 0.0f : -1e30f;

        // ---- stage Q-hi (16KB at base 0) and load A-fragments (both passes) ----
        #pragma unroll
        for (int i = 0; i < 4; ++i) {
            int fi = tid + i * THREADS;
            int row = fi >> 3, c8 = fi & 7;
            CP16(sb + swz((uint32_t)(row * 128 + c8 * 16)),
                 g_Qhi + ((size_t)bh * S + q0 + row) * Dh + c8 * 8);
        }
        CP_COMMIT(); CP_WAIT0(); __syncthreads();
        uint32_t qa[4][4];
        #pragma unroll
        for (int ks = 0; ks < 4; ++ks) {
            uint32_t a = sb +
                swz((uint32_t)((w * 16 + (lane & 15)) * 128 + ks * 32 +
                               ((lane >> 4) & 1) * 16));
            LDSM4(qa[ks], a);
        }
        __syncthreads();   // Q staging reads done; smem free for K/V tiles

        if (isA) {
            // ======== PASS A UNIT: rowsums (1-term fp16 qh*kh, mask folded in fma) ========
            float rs0 = 0.f, rs1 = 0.f;
            #pragma unroll
            for (int i = 0; i < 4; ++i) {   // preload K tile 0 (16KB, buffers at 0/16384)
                int fi = tid + i * THREADS;
                int row = fi >> 3, c8 = fi & 7;
                CP16(sb + swz((uint32_t)(row * 128 + c8 * 16)),
                     g_Khi + ((size_t)bh * S + row) * Dh + c8 * 8);
            }
            CP_COMMIT();
            for (int t = 0; t < NTA; ++t) {
                const int t0 = t * NKA;
                if (t + 1 < NTA) {
                    const uint32_t dstb = sb + ((t + 1) & 1) * 16384;
                    #pragma unroll
                    for (int i = 0; i < 4; ++i) {
                        int fi = tid + i * THREADS;
                        int row = fi >> 3, c8 = fi & 7;
                        CP16(dstb + swz((uint32_t)(row * 128 + c8 * 16)),
                             g_Khi + ((size_t)bh * S + t0 + NKA + row) * Dh + c8 * 8);
                    }
                    CP_COMMIT(); CP_WAIT1();
                } else {
                    CP_WAIT0();
                }
                __syncthreads();
                const uint32_t kbase = sb + (t & 1) * 16384;
                #pragma unroll
                for (int g = 0; g < 8; ++g) {
                    float c0[4] = {0.f, 0.f, 0.f, 0.f};
                    float c1[4] = {0.f, 0.f, 0.f, 0.f};
                    uint32_t rowb = g * 16 + (lane & 15);
                    #pragma unroll
                    for (int ks = 0; ks < 4; ++ks) {
                        uint32_t kh[4];
                        LDSM4(kh, kbase + swz(rowb * 128 + ks * 32 + ((lane >> 4) & 1) * 16));
                        mma_f16(c0, qa[ks], kh[0], kh[2]);
                        mma_f16(c1, qa[ks], kh[1], kh[3]);
                    }
                    int colA = t0 + g * 16 + 2 * (lane & 3);
                    float2 mA = *reinterpret_cast<const float2*>(msf + colA);
                    float2 mB = *reinterpret_cast<const float2*>(msf + colA + 8);
                    rs0 += ex2f(fmaf(c0[0], LOG2E, mA.x)) + ex2f(fmaf(c0[1], LOG2E, mA.y));
                    rs1 += ex2f(fmaf(c0[2], LOG2E, mA.x)) + ex2f(fmaf(c0[3], LOG2E, mA.y));
                    rs0 += ex2f(fmaf(c1[0], LOG2E, mB.x)) + ex2f(fmaf(c1[1], LOG2E, mB.y));
                    rs1 += ex2f(fmaf(c1[2], LOG2E, mB.x)) + ex2f(fmaf(c1[3], LOG2E, mB.y));
                }
                __syncthreads();
            }
            rs0 += __shfl_xor_sync(0xffffffffu, rs0, 1);
            rs0 += __shfl_xor_sync(0xffffffffu, rs0, 2);
            rs1 += __shfl_xor_sync(0xffffffffu, rs1, 1);
            rs1 += __shfl_xor_sync(0xffffffffu, rs1, 2);
            if ((lane & 3) == 0) {
                g_linv[u][w * 16 + (lane >> 2)]     = -__log2f(rs0);
                g_linv[u][w * 16 + 8 + (lane >> 2)] = -__log2f(rs1);
            }
            __syncthreads();
            __threadfence();                       // release: linv visible before flag
            if (tid == 0) atomicExch(&g_flag[u], 1u);
        } else {
            // ======== PASS B UNIT: p_attn + out (1-term fp16 QK, single-V PV) ========
            // acquire rowsums from the matching A unit
            if (tid == 0) {
                while (atomicAdd(&g_flag[u], 0u) == 0u) __nanosleep(200);
                __threadfence();
            }
            __syncthreads();
            const float linv0 = __ldcg(&g_linv[u][w * 16 + (lane >> 2)]);
            const float linv1 = __ldcg(&g_linv[u][w * 16 + 8 + (lane >> 2)]);

            float oacc[8][4];
            #pragma unroll
            for (int d = 0; d < 8; ++d)
                #pragma unroll
                for (int e = 0; e < 4; ++e) oacc[d][e] = 0.f;

            const int r0g = q0 + w * 16 + (lane >> 2);
            float* pa_row0 = p_attn + ((size_t)bh * S + r0g) * S;
            float* pa_row1 = p_attn + ((size_t)bh * S + r0g + 8) * S;

            auto loadB = [&](int t, int buf) {
                const int t0 = t * NK;
                const uint32_t kbuf = sb + buf * 8192;
                const uint32_t vbuf = sb + OFF_V + buf * 8192;
                #pragma unroll
                for (int i = 0; i < 2; ++i) {
                    int fi = tid + i * THREADS;
                    int row = fi >> 3, c8 = fi & 7;
                    uint32_t soff = swz((uint32_t)(row * 128 + c8 * 16));
                    CP16(kbuf + soff,
                         g_Khi + ((size_t)bh * S + t0 + row) * Dh + c8 * 8);
                    CP16(vbuf + soff,
                         g_VThi + ((size_t)bh * Dh + row) * S + t0 + c8 * 8);
                }
            };

            loadB(0, 0); CP_COMMIT();
            for (int t = 0; t < NT; ++t) {
                const int t0 = t * NK;
                if (t + 1 < NT) { loadB(t + 1, (t + 1) & 1); CP_COMMIT(); CP_WAIT1(); }
                else            { CP_WAIT0(); }
                __syncthreads();
                const uint32_t kb = sb + (t & 1) * 8192;
                const uint32_t vb = sb + OFF_V + (t & 1) * 8192;

                #pragma unroll
                for (int g = 0; g < 4; ++g) {
                    float c0[4] = {0.f, 0.f, 0.f, 0.f};
                    float c1[4] = {0.f, 0.f, 0.f, 0.f};
                    uint32_t rowb = g * 16 + (lane & 15);
                    #pragma unroll
                    for (int ks = 0; ks < 4; ++ks) {
                        uint32_t kh[4];
                        LDSM4(kh, kb + swz(rowb * 128 + ks * 32 + ((lane >> 4) & 1) * 16));
                        mma_f16(c0, qa[ks], kh[0], kh[2]);
                        mma_f16(c1, qa[ks], kh[1], kh[3]);
                    }
                    int colA = t0 + g * 16 + 2 * (lane & 3);
                    float2 mA = *reinterpret_cast<const float2*>(msf + colA);
                    float2 mB = *reinterpret_cast<const float2*>(msf + colA + 8);
                    float p00 = ex2f(fmaf(c0[0], LOG2E, linv0) + mA.x);
                    float p01 = ex2f(fmaf(c0[1], LOG2E, linv0) + mA.y);
                    float p10 = ex2f(fmaf(c0[2], LOG2E, linv1) + mA.x);
                    float p11 = ex2f(fmaf(c0[3], LOG2E, linv1) + mA.y);
                    float q00 = ex2f(fmaf(c1[0], LOG2E, linv0) + mB.x);
                    float q01 = ex2f(fmaf(c1[1], LOG2E, linv0) + mB.y);
                    float q10 = ex2f(fmaf(c1[2], LOG2E, linv1) + mB.x);
                    float q11 = ex2f(fmaf(c1[3], LOG2E, linv1) + mB.y);
                    *reinterpret_cast<float2*>(pa_row0 + colA)     = make_float2(p00, p01);
                    *reinterpret_cast<float2*>(pa_row0 + colA + 8) = make_float2(q00, q01);
                    *reinterpret_cast<float2*>(pa_row1 + colA)     = make_float2(p10, p11);
                    *reinterpret_cast<float2*>(pa_row1 + colA + 8) = make_float2(q10, q11);
                    uint32_t pa[4];
                    pa[0] = packh2(p00, p01);
                    pa[1] = packh2(p10, p11);
                    pa[2] = packh2(q00, q01);
                    pa[3] = packh2(q10, q11);
                    uint32_t kcb = g * 32 + ((lane >> 4) & 1) * 16;
                    #pragma unroll
                    for (int db2 = 0; db2 < 4; ++db2) {
                        uint32_t vh[4];
                        LDSM4(vh, vb + swz((uint32_t)((db2 * 16 + (lane & 15)) * 128) + kcb));
                        mma_f16(oacc[db2 * 2],     pa, vh[0], vh[2]);
                        mma_f16(oacc[db2 * 2 + 1], pa, vh[1], vh[3]);
                    }
                }
                __syncthreads();
            }
            #pragma unroll
            for (int db = 0; db < 8; ++db) {
                int col = db * 8 + 2 * (lane & 3);
                *reinterpret_cast<float2*>(out + ((size_t)bh * S + r0g) * Dh + col) =
                    make_float2(oacc[db][0], oacc[db][1]);
                *reinterpret_cast<float2*>(out + ((size_t)bh * S + r0g + 8) * Dh + col) =
                    make_float2(oacc[db][2], oacc[db][3]);
            }
        }
    }
}

extern "C" void kernel_launch(void* const* d_in, const int* in_sizes, int n_in,
                              void* d_out, int out_size) {
    const float* q = (const float*)d_in[0];
    const float* k = (const float*)d_in[1];
    const float* v = (const float*)d_in[2];
    const int* mask = (const int*)d_in[3];

    float* out = (float*)d_out;
    float* p_attn = out + (size_t)Bn * Hn * S * Dh;

    conv_all<<<QK_BLOCKS + VT_BLOCKS, THREADS>>>(q, k, v);

    cudaFuncSetAttribute(attn_persist, cudaFuncAttributeMaxDynamicSharedMemorySize, SMEM_BYTES);
    attn_persist<<<GRID, THREADS, SMEM_BYTES>>>(mask, out, p_attn);
}

// round 16
// speedup vs baseline: 1.6771x; 1.0409x over previous
#include <cuda_runtime.h>
#include <cuda_fp16.h>
#include <cstdint>

namespace {
constexpr int Bn = 4, Hn = 16, S = 2048, Dh = 64;
constexpr int BH = Bn * Hn;
constexpr int MQ = 128;           // pass B q rows per unit
constexpr int MQA = 256;          // pass A q rows per unit (M=32 per warp)
constexpr int NKA = 128;          // pass A keys per tile
constexpr int NTA = S / NKA;      // 16
constexpr int NK = 64;            // pass B keys per tile
constexpr int NT = S / NK;        // 32
constexpr int THREADS = 256;
constexpr int NELEM = BH * S * Dh;
constexpr float LOG2E = 1.4426950408889634f;
constexpr int NUNITS_A = BH * (S / MQA);  // 512
constexpr int NUNITS_B = BH * (S / MQ);   // 1024
constexpr int GRID = 296;                 // 2 CTAs/SM x 148 SMs (persistent)
constexpr int QK_BLOCKS = NELEM / 4 / THREADS;            // 8192
constexpr int VT_BLOCKS = (S / 32) * (Dh / 32) * BH;      // 8192

// smem: ring-3 buffers [0, 48KB); mask at 48KB
// pass A: K tiles 16KB at buf*16384 (buf = t%3); Q staged 32KB at 0 pre-loop
// pass B: K 8KB at buf*8192, V 8KB at 24576+buf*8192; Q staged 16KB at 0 pre-loop
constexpr int OFF_VB  = 24576;
constexpr int OFF_MS  = 49152;          // 2048 f32 (log-domain mask)
constexpr unsigned SMEM_BYTES = OFF_MS + S * 4;   // 57,344 B -> 2 CTAs/SM
}

__device__ __half g_Qhi[NELEM];
__device__ __half g_Khi[NELEM];
__device__ __half g_VThi[NELEM];   // [bh][d][s]

__device__ unsigned g_ctr;
__device__ unsigned g_flag[NUNITS_A];
__device__ float    g_linv_f[BH * S];   // per q-row -log2(rowsum)

__device__ __forceinline__ uint32_t s2u(const void* p) {
    uint32_t a;
    asm("{ .reg .u64 t; cvta.to.shared.u64 t, %1; cvt.u32.u64 %0, t; }" : "=r"(a) : "l"(p));
    return a;
}
__device__ __forceinline__ uint32_t swz(uint32_t o) { return o ^ ((o >> 3) & 0x70); }

#define LDSM4(r, a) \
    asm volatile("ldmatrix.sync.aligned.m8n8.x4.shared.b16 {%0,%1,%2,%3},[%4];" \
                 : "=r"((r)[0]), "=r"((r)[1]), "=r"((r)[2]), "=r"((r)[3]) : "r"(a))
#define CP16(dst, src) \
    asm volatile("cp.async.ca.shared.global [%0], [%1], 16;" :: "r"(dst), "l"(src))
#define CP_COMMIT() asm volatile("cp.async.commit_group;" ::: "memory")
#define CP_WAIT0()  asm volatile("cp.async.wait_group 0;" ::: "memory")
#define CP_WAIT1()  asm volatile("cp.async.wait_group 1;" ::: "memory")

__device__ __forceinline__ void mma_f16(float c[4], const uint32_t a[4],
                                        uint32_t b0, uint32_t b1) {
    asm volatile(
        "mma.sync.aligned.m16n8k16.row.col.f32.f16.f16.f32 "
        "{%0,%1,%2,%3},{%4,%5,%6,%7},{%8,%9},{%0,%1,%2,%3};"
        : "+f"(c[0]), "+f"(c[1]), "+f"(c[2]), "+f"(c[3])
        : "r"(a[0]), "r"(a[1]), "r"(a[2]), "r"(a[3]), "r"(b0), "r"(b1));
}

__device__ __forceinline__ float ex2f(float x) {
    float r;
    asm("ex2.approx.ftz.f32 %0, %1;" : "=f"(r) : "f"(x));
    return r;
}
// pack two f32 into f16x2: lo half = x, hi half = y
__device__ __forceinline__ uint32_t packh2(float x, float y) {
    uint32_t r;
    asm("cvt.rn.f16x2.f32 %0, %1, %2;" : "=r"(r) : "f"(y), "f"(x));
    return r;
}

// ---------------- fused pre-kernel: QK convert + V transpose ----------------
__global__ void conv_all(const float* __restrict__ q, const float* __restrict__ k,
                         const float* __restrict__ v) {
    __shared__ float t[32][33];
    const int bid = blockIdx.x;
    if (bid < QK_BLOCKS) {
        if (bid == 0) {
            if (threadIdx.x == 0) g_ctr = 0u;
            for (int i = threadIdx.x; i < NUNITS_A; i += blockDim.x) g_flag[i] = 0u;
        }
        size_t i4 = (size_t)bid * blockDim.x + threadIdx.x;
        size_t e = i4 * 4;
        float4 qv = *reinterpret_cast<const float4*>(q + e);
        float4 kv = *reinterpret_cast<const float4*>(k + e);
        qv.x *= 0.125f; qv.y *= 0.125f; qv.z *= 0.125f; qv.w *= 0.125f;
        uint2 wq;
        wq.x = packh2(qv.x, qv.y);
        wq.y = packh2(qv.z, qv.w);
        *reinterpret_cast<uint2*>(g_Qhi + e) = wq;
        uint2 wk;
        wk.x = packh2(kv.x, kv.y);
        wk.y = packh2(kv.z, kv.w);
        *reinterpret_cast<uint2*>(g_Khi + e) = wk;
    } else {
        const int vb = bid - QK_BLOCKS;
        const int bh = vb >> 7;
        const int rem = vb & 127;
        const int s0 = (rem >> 1) << 5;
        const int d0 = (rem & 1) << 5;
        const int tx = threadIdx.x & 31, ty = threadIdx.x >> 5;
        #pragma unroll
        for (int j = 0; j < 4; ++j)
            t[ty + 8 * j][tx] = v[((size_t)bh * S + s0 + ty + 8 * j) * Dh + d0 + tx];
        __syncthreads();
        #pragma unroll
        for (int j = 0; j < 4; ++j) {
            float x = t[tx][ty + 8 * j];
            size_t o = ((size_t)bh * Dh + d0 + ty + 8 * j) * S + s0 + tx;
            g_VThi[o] = __float2half_rn(x);
        }
    }
}

// ---------------- persistent main kernel ----------------
__global__ __launch_bounds__(THREADS, 2)
void attn_persist(const int* __restrict__ mask, float* __restrict__ out,
                  float* __restrict__ p_attn)
{
    extern __shared__ char sm[];
    __shared__ unsigned s_uid;
    const uint32_t sb = s2u(sm);
    const int tid = threadIdx.x;
    const int w = tid >> 5, lane = tid & 31;
    float* msf = reinterpret_cast<float*>(sm + OFF_MS);

    for (;;) {
        __syncthreads();   // previous unit fully done with smem + s_uid
        if (tid == 0) s_uid = atomicAdd(&g_ctr, 1u);
        __syncthreads();
        const unsigned uid = s_uid;
        if (uid >= (unsigned)(NUNITS_A + NUNITS_B)) break;
        const bool isA = uid < (unsigned)NUNITS_A;

        if (isA) {
            // ======== PASS A UNIT: rowsums, M=32 per warp (256 q rows) ========
            const int u  = (int)uid;
            const int qt = u & 7, bh = u >> 3;
            const int b  = bh >> 4;
            const int q0 = qt * MQA;

            for (int i = tid; i < S; i += THREADS)
                msf[i] = (mask[b * S + i] != 0) ? 0.0f : -1e30f;

            // stage Q (256 rows, 32KB at base 0)
            #pragma unroll
            for (int i = 0; i < 8; ++i) {
                int fi = tid + i * THREADS;
                int row = fi >> 3, c8 = fi & 7;
                CP16(sb + swz((uint32_t)(row * 128 + c8 * 16)),
                     g_Qhi + ((size_t)bh * S + q0 + row) * Dh + c8 * 8);
            }
            CP_COMMIT(); CP_WAIT0(); __syncthreads();
            uint32_t qa[2][4][4];   // 2 m-tiles: rows w*32+mt*16+..
            #pragma unroll
            for (int mt = 0; mt < 2; ++mt)
                #pragma unroll
                for (int ks = 0; ks < 4; ++ks) {
                    uint32_t a = sb +
                        swz((uint32_t)((w * 32 + mt * 16 + (lane & 15)) * 128 + ks * 32 +
                                       ((lane >> 4) & 1) * 16));
                    LDSM4(qa[mt][ks], a);
                }
            __syncthreads();   // Q staging reads done; smem free for K ring

            float rs[4] = {0.f, 0.f, 0.f, 0.f};
            #pragma unroll
            for (int i = 0; i < 4; ++i) {   // preload K tile 0 into buf0
                int fi = tid + i * THREADS;
                int row = fi >> 3, c8 = fi & 7;
                CP16(sb + swz((uint32_t)(row * 128 + c8 * 16)),
                     g_Khi + ((size_t)bh * S + row) * Dh + c8 * 8);
            }
            CP_COMMIT();
            for (int t = 0; t < NTA; ++t) {
                const int t0 = t * NKA;
                if (t + 1 < NTA) {
                    const uint32_t dstb = sb + ((t + 1) % 3) * 16384;
                    #pragma unroll
                    for (int i = 0; i < 4; ++i) {
                        int fi = tid + i * THREADS;
                        int row = fi >> 3, c8 = fi & 7;
                        CP16(dstb + swz((uint32_t)(row * 128 + c8 * 16)),
                             g_Khi + ((size_t)bh * S + t0 + NKA + row) * Dh + c8 * 8);
                    }
                    CP_COMMIT(); CP_WAIT1();
                } else {
                    CP_WAIT0();
                }
                __syncthreads();           // ring-3: single sync per tile
                const uint32_t kbase = sb + (t % 3) * 16384;
                #pragma unroll
                for (int g = 0; g < 8; ++g) {
                    float cA0[4] = {0.f, 0.f, 0.f, 0.f};
                    float cA1[4] = {0.f, 0.f, 0.f, 0.f};
                    float cB0[4] = {0.f, 0.f, 0.f, 0.f};
                    float cB1[4] = {0.f, 0.f, 0.f, 0.f};
                    uint32_t rowb = g * 16 + (lane & 15);
                    #pragma unroll
                    for (int ks = 0; ks < 4; ++ks) {
                        uint32_t kh[4];
                        LDSM4(kh, kbase + swz(rowb * 128 + ks * 32 + ((lane >> 4) & 1) * 16));
                        mma_f16(cA0, qa[0][ks], kh[0], kh[2]);
                        mma_f16(cA1, qa[0][ks], kh[1], kh[3]);
                        mma_f16(cB0, qa[1][ks], kh[0], kh[2]);
                        mma_f16(cB1, qa[1][ks], kh[1], kh[3]);
                    }
                    int colA = t0 + g * 16 + 2 * (lane & 3);
                    float2 mA = *reinterpret_cast<const float2*>(msf + colA);
                    float2 mB = *reinterpret_cast<const float2*>(msf + colA + 8);
                    rs[0] += ex2f(fmaf(cA0[0], LOG2E, mA.x)) + ex2f(fmaf(cA0[1], LOG2E, mA.y));
                    rs[1] += ex2f(fmaf(cA0[2], LOG2E, mA.x)) + ex2f(fmaf(cA0[3], LOG2E, mA.y));
                    rs[0] += ex2f(fmaf(cA1[0], LOG2E, mB.x)) + ex2f(fmaf(cA1[1], LOG2E, mB.y));
                    rs[1] += ex2f(fmaf(cA1[2], LOG2E, mB.x)) + ex2f(fmaf(cA1[3], LOG2E, mB.y));
                    rs[2] += ex2f(fmaf(cB0[0], LOG2E, mA.x)) + ex2f(fmaf(cB0[1], LOG2E, mA.y));
                    rs[3] += ex2f(fmaf(cB0[2], LOG2E, mA.x)) + ex2f(fmaf(cB0[3], LOG2E, mA.y));
                    rs[2] += ex2f(fmaf(cB1[0], LOG2E, mB.x)) + ex2f(fmaf(cB1[1], LOG2E, mB.y));
                    rs[3] += ex2f(fmaf(cB1[2], LOG2E, mB.x)) + ex2f(fmaf(cB1[3], LOG2E, mB.y));
                }
            }
            #pragma unroll
            for (int r = 0; r < 4; ++r) {
                rs[r] += __shfl_xor_sync(0xffffffffu, rs[r], 1);
                rs[r] += __shfl_xor_sync(0xffffffffu, rs[r], 2);
            }
            if ((lane & 3) == 0) {
                int rbase = bh * S + q0 + w * 32;
                g_linv_f[rbase + (lane >> 2)]          = -__log2f(rs[0]);
                g_linv_f[rbase + 8 + (lane >> 2)]      = -__log2f(rs[1]);
                g_linv_f[rbase + 16 + (lane >> 2)]     = -__log2f(rs[2]);
                g_linv_f[rbase + 24 + (lane >> 2)]     = -__log2f(rs[3]);
            }
            __syncthreads();
            __threadfence();                       // release: linv visible before flag
            if (tid == 0) atomicExch(&g_flag[u], 1u);
        } else {
            // ======== PASS B UNIT: p_attn + out (1-term fp16 QK, single-V PV) ========
            const int u  = (int)(uid - NUNITS_A);
            const int qt = u & 15, bh = u >> 4;
            const int b  = bh >> 4;
            const int q0 = qt * MQ;
            const int fb = bh * 8 + (qt >> 1);     // matching A-unit flag

            for (int i = tid; i < S; i += THREADS)
                msf[i] = (mask[b * S + i] != 0) ? 0.0f : -1e30f;

            // stage Q (128 rows, 16KB at base 0)
            #pragma unroll
            for (int i = 0; i < 4; ++i) {
                int fi = tid + i * THREADS;
                int row = fi >> 3, c8 = fi & 7;
                CP16(sb + swz((uint32_t)(row * 128 + c8 * 16)),
                     g_Qhi + ((size_t)bh * S + q0 + row) * Dh + c8 * 8);
            }
            CP_COMMIT(); CP_WAIT0(); __syncthreads();
            uint32_t qa[4][4];
            #pragma unroll
            for (int ks = 0; ks < 4; ++ks) {
                uint32_t a = sb +
                    swz((uint32_t)((w * 16 + (lane & 15)) * 128 + ks * 32 +
                                   ((lane >> 4) & 1) * 16));
                LDSM4(qa[ks], a);
            }
            // acquire rowsums from the matching A unit
            if (tid == 0) {
                while (atomicAdd(&g_flag[fb], 0u) == 0u) __nanosleep(200);
                __threadfence();
            }
            __syncthreads();   // Q staging reads done + flag acquired
            const float linv0 = __ldcg(&g_linv_f[bh * S + q0 + w * 16 + (lane >> 2)]);
            const float linv1 = __ldcg(&g_linv_f[bh * S + q0 + w * 16 + 8 + (lane >> 2)]);

            float oacc[8][4];
            #pragma unroll
            for (int d = 0; d < 8; ++d)
                #pragma unroll
                for (int e = 0; e < 4; ++e) oacc[d][e] = 0.f;

            const int r0g = q0 + w * 16 + (lane >> 2);
            float* pa_row0 = p_attn + ((size_t)bh * S + r0g) * S;
            float* pa_row1 = p_attn + ((size_t)bh * S + r0g + 8) * S;

            auto loadB = [&](int t, int buf) {
                const int t0 = t * NK;
                const uint32_t kbuf = sb + buf * 8192;
                const uint32_t vbuf = sb + OFF_VB + buf * 8192;
                #pragma unroll
                for (int i = 0; i < 2; ++i) {
                    int fi = tid + i * THREADS;
                    int row = fi >> 3, c8 = fi & 7;
                    uint32_t soff = swz((uint32_t)(row * 128 + c8 * 16));
                    CP16(kbuf + soff,
                         g_Khi + ((size_t)bh * S + t0 + row) * Dh + c8 * 8);
                    CP16(vbuf + soff,
                         g_VThi + ((size_t)bh * Dh + row) * S + t0 + c8 * 8);
                }
            };

            loadB(0, 0); CP_COMMIT();
            for (int t = 0; t < NT; ++t) {
                const int t0 = t * NK;
                if (t + 1 < NT) { loadB(t + 1, (t + 1) % 3); CP_COMMIT(); CP_WAIT1(); }
                else            { CP_WAIT0(); }
                __syncthreads();           // ring-3: single sync per tile
                const uint32_t kb = sb + (t % 3) * 8192;
                const uint32_t vb = sb + OFF_VB + (t % 3) * 8192;

                #pragma unroll
                for (int g = 0; g < 4; ++g) {
                    float c0[4] = {0.f, 0.f, 0.f, 0.f};
                    float c1[4] = {0.f, 0.f, 0.f, 0.f};
                    uint32_t rowb = g * 16 + (lane & 15);
                    #pragma unroll
                    for (int ks = 0; ks < 4; ++ks) {
                        uint32_t kh[4];
                        LDSM4(kh, kb + swz(rowb * 128 + ks * 32 + ((lane >> 4) & 1) * 16));
                        mma_f16(c0, qa[ks], kh[0], kh[2]);
                        mma_f16(c1, qa[ks], kh[1], kh[3]);
                    }
                    int colA = t0 + g * 16 + 2 * (lane & 3);
                    float2 mA = *reinterpret_cast<const float2*>(msf + colA);
                    float2 mB = *reinterpret_cast<const float2*>(msf + colA + 8);
                    float p00 = ex2f(fmaf(c0[0], LOG2E, linv0) + mA.x);
                    float p01 = ex2f(fmaf(c0[1], LOG2E, linv0) + mA.y);
                    float p10 = ex2f(fmaf(c0[2], LOG2E, linv1) + mA.x);
                    float p11 = ex2f(fmaf(c0[3], LOG2E, linv1) + mA.y);
                    float q00 = ex2f(fmaf(c1[0], LOG2E, linv0) + mB.x);
                    float q01 = ex2f(fmaf(c1[1], LOG2E, linv0) + mB.y);
                    float q10 = ex2f(fmaf(c1[2], LOG2E, linv1) + mB.x);
                    float q11 = ex2f(fmaf(c1[3], LOG2E, linv1) + mB.y);
                    *reinterpret_cast<float2*>(pa_row0 + colA)     = make_float2(p00, p01);
                    *reinterpret_cast<float2*>(pa_row0 + colA + 8) = make_float2(q00, q01);
                    *reinterpret_cast<float2*>(pa_row1 + colA)     = make_float2(p10, p11);
                    *reinterpret_cast<float2*>(pa_row1 + colA + 8) = make_float2(q10, q11);
                    uint32_t pa[4];
                    pa[0] = packh2(p00, p01);
                    pa[1] = packh2(p10, p11);
                    pa[2] = packh2(q00, q01);
                    pa[3] = packh2(q10, q11);
                    uint32_t kcb = g * 32 + ((lane >> 4) & 1) * 16;
                    #pragma unroll
                    for (int db2 = 0; db2 < 4; ++db2) {
                        uint32_t vh[4];
                        LDSM4(vh, vb + swz((uint32_t)((db2 * 16 + (lane & 15)) * 128) + kcb));
                        mma_f16(oacc[db2 * 2],     pa, vh[0], vh[2]);
                        mma_f16(oacc[db2 * 2 + 1], pa, vh[1], vh[3]);
                    }
                }
            }
            #pragma unroll
            for (int db = 0; db < 8; ++db) {
                int col = db * 8 + 2 * (lane & 3);
                *reinterpret_cast<float2*>(out + ((size_t)bh * S + r0g) * Dh + col) =
                    make_float2(oacc[db][0], oacc[db][1]);
                *reinterpret_cast<float2*>(out + ((size_t)bh * S + r0g + 8) * Dh + col) =
                    make_float2(oacc[db][2], oacc[db][3]);
            }
        }
    }
}

extern "C" void kernel_launch(void* const* d_in, const int* in_sizes, int n_in,
                              void* d_out, int out_size) {
    const float* q = (const float*)d_in[0];
    const float* k = (const float*)d_in[1];
    const float* v = (const float*)d_in[2];
    const int* mask = (const int*)d_in[3];

    float* out = (float*)d_out;
    float* p_attn = out + (size_t)Bn * Hn * S * Dh;

    conv_all<<<QK_BLOCKS + VT_BLOCKS, THREADS>>>(q, k, v);

    cudaFuncSetAttribute(attn_persist, cudaFuncAttributeMaxDynamicSharedMemorySize, SMEM_BYTES);
    attn_persist<<<GRID, THREADS, SMEM_BYTES>>>(mask, out, p_attn);
}